// round 4
// baseline (speedup 1.0000x reference)
#include <cuda_runtime.h>
#include <cuda_bf16.h>
#include <cstdint>

#define NNODES 100000
#define EMAX   1600000
#define KDIM   128

// ---------------- scratch (no allocation allowed) ----------------
__device__ __align__(16) float g_dinv[NNODES];
__device__            int   g_deg[NNODES];       // edge-only in-degree (no self loop)
__device__            int   g_off[NNODES + 1];   // CSR offsets
__device__            int   g_cur[NNODES];       // fill cursors
__device__            int   g_srcl[EMAX];        // CSR src lists (bucketed by dst)
__device__ __align__(16) float g_tmp1[(size_t)NNODES * 128];  // dinv*h (layer1), then dinv*h2 (layer2, N*64)
__device__ __align__(16) float g_acc1[(size_t)NNODES * 128];  // relu'd layer1 output (N*128)

// ---------------- degree / dinv ----------------
__global__ void deg_init_kernel(int n) {
    int i = blockIdx.x * blockDim.x + threadIdx.x;
    if (i < n) g_deg[i] = 0;
}

__global__ void deg_count_kernel(const int* __restrict__ dst, int E) {
    int i = blockIdx.x * blockDim.x + threadIdx.x;
    if (i < E) atomicAdd(&g_deg[dst[i]], 1);
}

__global__ void dinv_kernel(int n) {
    int i = blockIdx.x * blockDim.x + threadIdx.x;
    if (i < n) g_dinv[i] = rsqrtf((float)g_deg[i] + 1.0f);   // +1 self loop
}

// ---------------- exclusive scan (single block, 1024 threads) ----------------
__global__ void scan_kernel(int n) {
    __shared__ int sp[1024];
    int tid = threadIdx.x;
    int chunk = (n + 1023) >> 10;
    int st = tid * chunk;
    int en = st + chunk; if (en > n) en = n;
    int s = 0;
    for (int i = st; i < en; i++) s += g_deg[i];
    sp[tid] = s;
    __syncthreads();
    for (int off = 1; off < 1024; off <<= 1) {
        int v = (tid >= off) ? sp[tid - off] : 0;
        __syncthreads();
        sp[tid] += v;
        __syncthreads();
    }
    int base = (tid == 0) ? 0 : sp[tid - 1];
    for (int i = st; i < en; i++) {
        g_off[i] = base;
        g_cur[i] = 0;
        base += g_deg[i];
    }
    if (en == n && st < n) g_off[n] = base;
    if (tid == 1023 && st >= n) g_off[n] = sp[1023];
}

// ---------------- CSR fill ----------------
__global__ void fill_kernel(const int* __restrict__ src,
                            const int* __restrict__ dst, int E) {
    int i = blockIdx.x * blockDim.x + threadIdx.x;
    if (i < E) {
        int d = dst[i];
        int pos = atomicAdd(&g_cur[d], 1);
        g_srcl[g_off[d] + pos] = src[i];
    }
}

// ---------------- GEMM with dinv-scaled epilogue (packed f32x2 FMA) --------
// writes g_tmp1[r,:] = dinv[r] * (A[r,:] @ W),  A: [M,128], W: [128,NN]
// GIN: if true, A comes from g_acc1 (ignore Ap).
template<int NN, bool GIN>
__global__ __launch_bounds__(256) void gemm_scale_kernel(
        const float* __restrict__ Ap,
        const float* __restrict__ W, int M)
{
    constexpr int TN = NN / 32;     // 4 (NN=128) or 2 (NN=64)
    constexpr int BM = 64, TM = 8;
    extern __shared__ float sm[];
    float* Ws = sm;                 // KDIM*NN
    float* As = sm + KDIM * NN;     // BM*KDIM

    const float* A = GIN ? (const float*)g_acc1 : Ap;

    int tid = threadIdx.x;          // 256 threads
    for (int idx = tid; idx < KDIM * NN / 4; idx += 256)
        ((float4*)Ws)[idx] = ((const float4*)W)[idx];
    int m0 = blockIdx.x * BM;
    for (int idx = tid; idx < BM * (KDIM / 4); idx += 256) {
        int r = idx / (KDIM / 4);
        int c = idx % (KDIM / 4);
        float4 v = make_float4(0.f, 0.f, 0.f, 0.f);
        if (m0 + r < M) v = ((const float4*)(A + (size_t)(m0 + r) * KDIM))[c];
        ((float4*)(As + r * KDIM))[c] = v;
    }
    __syncthreads();

    int tx = tid & 31, ty = tid >> 5;
    unsigned long long acc[TM][TN / 2];
#pragma unroll
    for (int i = 0; i < TM; i++)
#pragma unroll
        for (int j = 0; j < TN / 2; j++) acc[i][j] = 0ull;

#pragma unroll 2
    for (int k = 0; k < KDIM; k += 4) {
        float4 a4[TM];
#pragma unroll
        for (int i = 0; i < TM; i++)
            a4[i] = *(const float4*)&As[(ty * TM + i) * KDIM + k];
#pragma unroll
        for (int kk = 0; kk < 4; kk++) {
            unsigned long long bp[TN / 2];
            if constexpr (TN == 4) {
                float4 bb = ((const float4*)(Ws + (k + kk) * NN))[tx];
                asm("mov.b64 %0, {%1,%2};" : "=l"(bp[0]) : "f"(bb.x), "f"(bb.y));
                asm("mov.b64 %0, {%1,%2};" : "=l"(bp[1]) : "f"(bb.z), "f"(bb.w));
            } else {
                float2 bb = ((const float2*)(Ws + (k + kk) * NN))[tx];
                asm("mov.b64 %0, {%1,%2};" : "=l"(bp[0]) : "f"(bb.x), "f"(bb.y));
            }
#pragma unroll
            for (int i = 0; i < TM; i++) {
                float av = (kk == 0) ? a4[i].x : (kk == 1) ? a4[i].y
                         : (kk == 2) ? a4[i].z : a4[i].w;
                unsigned long long a2;
                asm("mov.b64 %0, {%1,%1};" : "=l"(a2) : "f"(av));
#pragma unroll
                for (int j = 0; j < TN / 2; j++)
                    asm("fma.rn.f32x2 %0, %1, %2, %0;" : "+l"(acc[i][j]) : "l"(a2), "l"(bp[j]));
            }
        }
    }

#pragma unroll
    for (int i = 0; i < TM; i++) {
        int r = m0 + ty * TM + i;
        if (r < M) {
            float s = g_dinv[r];
            float v[4];
            asm("mov.b64 {%0,%1}, %2;" : "=f"(v[0]), "=f"(v[1]) : "l"(acc[i][0]));
            if constexpr (TN == 4) {
                asm("mov.b64 {%0,%1}, %2;" : "=f"(v[2]), "=f"(v[3]) : "l"(acc[i][1]));
                float4 o = make_float4(v[0] * s, v[1] * s, v[2] * s, v[3] * s);
                ((float4*)(g_tmp1 + (size_t)r * NN))[tx] = o;
            } else {
                float2 o = make_float2(v[0] * s, v[1] * s);
                ((float2*)(g_tmp1 + (size_t)r * NN))[tx] = o;
            }
        }
    }
}

// ---------------- gather aggregation ----------------
// layer 1: one warp per node; sum = tmp1[d] + sum_{s in CSR[d]} tmp1[s];
// g_acc1[d] = relu(dinv[d]*sum + b1)
__global__ void agg1_kernel(const float* __restrict__ b1, int n) {
    int w = (int)((blockIdx.x * (unsigned)blockDim.x + threadIdx.x) >> 5);
    int lane = threadIdx.x & 31;
    if (w >= n) return;
    const float4* base = (const float4*)g_tmp1;
    float4 sum = base[(size_t)w * 32 + lane];   // self loop
    int j = g_off[w], end = g_off[w + 1];
    for (; j + 4 <= end; j += 4) {
        int s0 = g_srcl[j], s1 = g_srcl[j + 1], s2 = g_srcl[j + 2], s3 = g_srcl[j + 3];
        float4 v0 = base[(size_t)s0 * 32 + lane];
        float4 v1 = base[(size_t)s1 * 32 + lane];
        float4 v2 = base[(size_t)s2 * 32 + lane];
        float4 v3 = base[(size_t)s3 * 32 + lane];
        sum.x += v0.x + v1.x + v2.x + v3.x;
        sum.y += v0.y + v1.y + v2.y + v3.y;
        sum.z += v0.z + v1.z + v2.z + v3.z;
        sum.w += v0.w + v1.w + v2.w + v3.w;
    }
    for (; j < end; j++) {
        int s = g_srcl[j];
        float4 v = base[(size_t)s * 32 + lane];
        sum.x += v.x; sum.y += v.y; sum.z += v.z; sum.w += v.w;
    }
    float sc = g_dinv[w];
    float4 bb = ((const float4*)b1)[lane];
    float4 o;
    o.x = fmaxf(fmaf(sc, sum.x, bb.x), 0.f);
    o.y = fmaxf(fmaf(sc, sum.y, bb.y), 0.f);
    o.z = fmaxf(fmaf(sc, sum.z, bb.z), 0.f);
    o.w = fmaxf(fmaf(sc, sum.w, bb.w), 0.f);
    ((float4*)g_acc1)[(size_t)w * 32 + lane] = o;
}

// layer 2: two nodes per warp (16 lanes each, 64 floats); out = dinv*sum + b2
__global__ void agg2_kernel(const float* __restrict__ b2, float* __restrict__ out, int n) {
    int w = (int)((blockIdx.x * (unsigned)blockDim.x + threadIdx.x) >> 5);
    int lane = threadIdx.x & 31;
    int d = w * 2 + (lane >> 4);
    int hl = lane & 15;
    if (d >= n) return;
    const float4* base = (const float4*)g_tmp1;
    float4 sum = base[(size_t)d * 16 + hl];     // self loop
    int j = g_off[d], end = g_off[d + 1];
    for (; j + 4 <= end; j += 4) {
        int s0 = g_srcl[j], s1 = g_srcl[j + 1], s2 = g_srcl[j + 2], s3 = g_srcl[j + 3];
        float4 v0 = base[(size_t)s0 * 16 + hl];
        float4 v1 = base[(size_t)s1 * 16 + hl];
        float4 v2 = base[(size_t)s2 * 16 + hl];
        float4 v3 = base[(size_t)s3 * 16 + hl];
        sum.x += v0.x + v1.x + v2.x + v3.x;
        sum.y += v0.y + v1.y + v2.y + v3.y;
        sum.z += v0.z + v1.z + v2.z + v3.z;
        sum.w += v0.w + v1.w + v2.w + v3.w;
    }
    for (; j < end; j++) {
        int s = g_srcl[j];
        float4 v = base[(size_t)s * 16 + hl];
        sum.x += v.x; sum.y += v.y; sum.z += v.z; sum.w += v.w;
    }
    float sc = g_dinv[d];
    float4 bb = ((const float4*)b2)[hl];
    float4 o;
    o.x = fmaf(sc, sum.x, bb.x);
    o.y = fmaf(sc, sum.y, bb.y);
    o.z = fmaf(sc, sum.z, bb.z);
    o.w = fmaf(sc, sum.w, bb.w);
    ((float4*)out)[(size_t)d * 16 + hl] = o;
}

// ---------------- launch ----------------
extern "C" void kernel_launch(void* const* d_in, const int* in_sizes, int n_in,
                              void* d_out, int out_size)
{
    const float* x  = (const float*)d_in[0];
    const int*   ei = (const int*)d_in[1];     // int32! (JAX coerces int64->int32)
    const float* W1 = (const float*)d_in[2];
    const float* b1 = (const float*)d_in[3];
    const float* W2 = (const float*)d_in[4];
    const float* b2 = (const float*)d_in[5];
    float* out = (float*)d_out;

    int n = in_sizes[0] / 128;   // 100000
    int E = in_sizes[1] / 2;     // 1600000
    const int* src = ei;
    const int* dst = ei + E;

    cudaFuncSetAttribute(gemm_scale_kernel<128, false>, cudaFuncAttributeMaxDynamicSharedMemorySize, 98304);
    cudaFuncSetAttribute(gemm_scale_kernel<64, true>,   cudaFuncAttributeMaxDynamicSharedMemorySize, 65536);

    // graph structure (rebuilt every call: deterministic work)
    deg_init_kernel <<<(n + 255) / 256, 256>>>(n);
    deg_count_kernel<<<(E + 255) / 256, 256>>>(dst, E);
    dinv_kernel     <<<(n + 255) / 256, 256>>>(n);
    scan_kernel     <<<1, 1024>>>(n);
    fill_kernel     <<<(E + 255) / 256, 256>>>(src, dst, E);

    // layer 1
    gemm_scale_kernel<128, false><<<(n + 63) / 64, 256, 98304>>>(x, W1, n);
    agg1_kernel<<<(n * 32 + 255) / 256, 256>>>(b1, n);

    // layer 2
    gemm_scale_kernel<64, true><<<(n + 63) / 64, 256, 65536>>>(nullptr, W2, n);
    {
        int warps = (n + 1) / 2;
        agg2_kernel<<<(warps * 32 + 255) / 256, 256>>>(b2, out, n);
    }
}

// round 5
// speedup vs baseline: 1.5589x; 1.5589x over previous
#include <cuda_runtime.h>
#include <cuda_bf16.h>
#include <cstdint>

#define NNODES 100000
#define EMAX   1600000
#define KDIM   128
#define SCAN_B 1024
#define NBLK   ((NNODES + SCAN_B - 1) / SCAN_B)   // 98

// ---------------- scratch (no allocation allowed) ----------------
__device__ __align__(16) float g_dinv[NNODES];
__device__            int   g_deg[NNODES];       // edge-only in-degree (no self loop)
__device__            int   g_off[NNODES + 1];   // CSR offsets
__device__            int   g_cur[NNODES];       // fill cursors
__device__            int   g_srcl[EMAX];        // CSR src lists (bucketed by dst)
__device__            int   g_bsum[128];
__device__            int   g_bpre[128];
__device__ __align__(16) float g_tmp1[(size_t)NNODES * 128];  // dinv*h (layer1), then dinv*h2 (layer2, N*64)
__device__ __align__(16) float g_acc1[(size_t)NNODES * 128];  // relu'd layer1 output (N*128)

// ---------------- degree ----------------
__global__ void deg_init_kernel(int n) {
    int i = blockIdx.x * blockDim.x + threadIdx.x;
    if (i < n) g_deg[i] = 0;
}

__global__ void deg_count_kernel(const int* __restrict__ dst, int E) {
    int i = blockIdx.x * blockDim.x + threadIdx.x;
    if (i < E) atomicAdd(&g_deg[dst[i]], 1);
}

// ---------------- multi-block exclusive scan ----------------
// phase 1: per-block scan + dinv computation
__global__ __launch_bounds__(SCAN_B) void scan1_kernel(int n) {
    __shared__ int sp[SCAN_B];
    int t = threadIdx.x;
    int i = blockIdx.x * SCAN_B + t;
    int d = (i < n) ? g_deg[i] : 0;
    if (i < n) g_dinv[i] = rsqrtf((float)d + 1.0f);   // +1 self loop
    sp[t] = d;
    __syncthreads();
#pragma unroll
    for (int off = 1; off < SCAN_B; off <<= 1) {
        int v = (t >= off) ? sp[t - off] : 0;
        __syncthreads();
        sp[t] += v;
        __syncthreads();
    }
    if (i < n) g_off[i] = sp[t] - d;      // exclusive within block
    if (t == SCAN_B - 1) g_bsum[blockIdx.x] = sp[t];
}

// phase 2: scan block sums (single small block)
__global__ void scan2_kernel(int nb, int n) {
    __shared__ int sp[128];
    int t = threadIdx.x;
    int v = (t < nb) ? g_bsum[t] : 0;
    sp[t] = v;
    __syncthreads();
#pragma unroll
    for (int off = 1; off < 128; off <<= 1) {
        int u = (t >= off) ? sp[t - off] : 0;
        __syncthreads();
        sp[t] += u;
        __syncthreads();
    }
    if (t < nb) g_bpre[t] = sp[t] - v;    // exclusive
    if (t == nb - 1) g_off[n] = sp[t];    // grand total
}

// phase 3: add block prefix, zero cursors
__global__ __launch_bounds__(SCAN_B) void scan3_kernel(int n) {
    int i = blockIdx.x * SCAN_B + threadIdx.x;
    if (i < n) {
        g_off[i] += g_bpre[blockIdx.x];
        g_cur[i] = 0;
    }
}

// ---------------- CSR fill ----------------
__global__ void fill_kernel(const int* __restrict__ src,
                            const int* __restrict__ dst, int E) {
    int i = blockIdx.x * blockDim.x + threadIdx.x;
    if (i < E) {
        int d = dst[i];
        int pos = atomicAdd(&g_cur[d], 1);
        g_srcl[g_off[d] + pos] = src[i];
    }
}

// ---------------- GEMM with dinv-scaled epilogue (packed f32x2 FMA) --------
// writes g_tmp1[r,:] = dinv[r] * (A[r,:] @ W),  A: [M,128], W: [128,NN]
// GIN: if true, A comes from g_acc1 (ignore Ap).
template<int NN, bool GIN>
__global__ __launch_bounds__(256) void gemm_scale_kernel(
        const float* __restrict__ Ap,
        const float* __restrict__ W, int M)
{
    constexpr int TN = NN / 32;     // 4 (NN=128) or 2 (NN=64)
    constexpr int BM = 64, TM = 8;
    extern __shared__ float sm[];
    float* Ws = sm;                 // KDIM*NN
    float* As = sm + KDIM * NN;     // BM*KDIM

    const float* A = GIN ? (const float*)g_acc1 : Ap;

    int tid = threadIdx.x;          // 256 threads
    for (int idx = tid; idx < KDIM * NN / 4; idx += 256)
        ((float4*)Ws)[idx] = ((const float4*)W)[idx];
    int m0 = blockIdx.x * BM;
    for (int idx = tid; idx < BM * (KDIM / 4); idx += 256) {
        int r = idx / (KDIM / 4);
        int c = idx % (KDIM / 4);
        float4 v = make_float4(0.f, 0.f, 0.f, 0.f);
        if (m0 + r < M) v = ((const float4*)(A + (size_t)(m0 + r) * KDIM))[c];
        ((float4*)(As + r * KDIM))[c] = v;
    }
    __syncthreads();

    int tx = tid & 31, ty = tid >> 5;
    unsigned long long acc[TM][TN / 2];
#pragma unroll
    for (int i = 0; i < TM; i++)
#pragma unroll
        for (int j = 0; j < TN / 2; j++) acc[i][j] = 0ull;

#pragma unroll 2
    for (int k = 0; k < KDIM; k += 4) {
        float4 a4[TM];
#pragma unroll
        for (int i = 0; i < TM; i++)
            a4[i] = *(const float4*)&As[(ty * TM + i) * KDIM + k];
#pragma unroll
        for (int kk = 0; kk < 4; kk++) {
            unsigned long long bp[TN / 2];
            if constexpr (TN == 4) {
                float4 bb = ((const float4*)(Ws + (k + kk) * NN))[tx];
                asm("mov.b64 %0, {%1,%2};" : "=l"(bp[0]) : "f"(bb.x), "f"(bb.y));
                asm("mov.b64 %0, {%1,%2};" : "=l"(bp[1]) : "f"(bb.z), "f"(bb.w));
            } else {
                float2 bb = ((const float2*)(Ws + (k + kk) * NN))[tx];
                asm("mov.b64 %0, {%1,%2};" : "=l"(bp[0]) : "f"(bb.x), "f"(bb.y));
            }
#pragma unroll
            for (int i = 0; i < TM; i++) {
                float av = (kk == 0) ? a4[i].x : (kk == 1) ? a4[i].y
                         : (kk == 2) ? a4[i].z : a4[i].w;
                unsigned long long a2;
                asm("mov.b64 %0, {%1,%1};" : "=l"(a2) : "f"(av));
#pragma unroll
                for (int j = 0; j < TN / 2; j++)
                    asm("fma.rn.f32x2 %0, %1, %2, %0;" : "+l"(acc[i][j]) : "l"(a2), "l"(bp[j]));
            }
        }
    }

#pragma unroll
    for (int i = 0; i < TM; i++) {
        int r = m0 + ty * TM + i;
        if (r < M) {
            float s = g_dinv[r];
            float v[4];
            asm("mov.b64 {%0,%1}, %2;" : "=f"(v[0]), "=f"(v[1]) : "l"(acc[i][0]));
            if constexpr (TN == 4) {
                asm("mov.b64 {%0,%1}, %2;" : "=f"(v[2]), "=f"(v[3]) : "l"(acc[i][1]));
                float4 o = make_float4(v[0] * s, v[1] * s, v[2] * s, v[3] * s);
                ((float4*)(g_tmp1 + (size_t)r * NN))[tx] = o;
            } else {
                float2 o = make_float2(v[0] * s, v[1] * s);
                ((float2*)(g_tmp1 + (size_t)r * NN))[tx] = o;
            }
        }
    }
}

// ---------------- gather aggregation ----------------
// layer 1: one warp per node; sum = tmp1[d] + sum_{s in CSR[d]} tmp1[s];
// g_acc1[d] = relu(dinv[d]*sum + b1)
__global__ void agg1_kernel(const float* __restrict__ b1, int n) {
    int w = (int)((blockIdx.x * (unsigned)blockDim.x + threadIdx.x) >> 5);
    int lane = threadIdx.x & 31;
    if (w >= n) return;
    const float4* base = (const float4*)g_tmp1;
    float4 sum = base[(size_t)w * 32 + lane];   // self loop
    int j = g_off[w], end = g_off[w + 1];
    for (; j + 4 <= end; j += 4) {
        int s0 = g_srcl[j], s1 = g_srcl[j + 1], s2 = g_srcl[j + 2], s3 = g_srcl[j + 3];
        float4 v0 = base[(size_t)s0 * 32 + lane];
        float4 v1 = base[(size_t)s1 * 32 + lane];
        float4 v2 = base[(size_t)s2 * 32 + lane];
        float4 v3 = base[(size_t)s3 * 32 + lane];
        sum.x += v0.x + v1.x + v2.x + v3.x;
        sum.y += v0.y + v1.y + v2.y + v3.y;
        sum.z += v0.z + v1.z + v2.z + v3.z;
        sum.w += v0.w + v1.w + v2.w + v3.w;
    }
    for (; j < end; j++) {
        int s = g_srcl[j];
        float4 v = base[(size_t)s * 32 + lane];
        sum.x += v.x; sum.y += v.y; sum.z += v.z; sum.w += v.w;
    }
    float sc = g_dinv[w];
    float4 bb = ((const float4*)b1)[lane];
    float4 o;
    o.x = fmaxf(fmaf(sc, sum.x, bb.x), 0.f);
    o.y = fmaxf(fmaf(sc, sum.y, bb.y), 0.f);
    o.z = fmaxf(fmaf(sc, sum.z, bb.z), 0.f);
    o.w = fmaxf(fmaf(sc, sum.w, bb.w), 0.f);
    ((float4*)g_acc1)[(size_t)w * 32 + lane] = o;
}

// layer 2: two nodes per warp (16 lanes each, 64 floats); out = dinv*sum + b2
__global__ void agg2_kernel(const float* __restrict__ b2, float* __restrict__ out, int n) {
    int w = (int)((blockIdx.x * (unsigned)blockDim.x + threadIdx.x) >> 5);
    int lane = threadIdx.x & 31;
    int d = w * 2 + (lane >> 4);
    int hl = lane & 15;
    if (d >= n) return;
    const float4* base = (const float4*)g_tmp1;
    float4 sum = base[(size_t)d * 16 + hl];     // self loop
    int j = g_off[d], end = g_off[d + 1];
    for (; j + 4 <= end; j += 4) {
        int s0 = g_srcl[j], s1 = g_srcl[j + 1], s2 = g_srcl[j + 2], s3 = g_srcl[j + 3];
        float4 v0 = base[(size_t)s0 * 16 + hl];
        float4 v1 = base[(size_t)s1 * 16 + hl];
        float4 v2 = base[(size_t)s2 * 16 + hl];
        float4 v3 = base[(size_t)s3 * 16 + hl];
        sum.x += v0.x + v1.x + v2.x + v3.x;
        sum.y += v0.y + v1.y + v2.y + v3.y;
        sum.z += v0.z + v1.z + v2.z + v3.z;
        sum.w += v0.w + v1.w + v2.w + v3.w;
    }
    for (; j < end; j++) {
        int s = g_srcl[j];
        float4 v = base[(size_t)s * 16 + hl];
        sum.x += v.x; sum.y += v.y; sum.z += v.z; sum.w += v.w;
    }
    float sc = g_dinv[d];
    float4 bb = ((const float4*)b2)[hl];
    float4 o;
    o.x = fmaf(sc, sum.x, bb.x);
    o.y = fmaf(sc, sum.y, bb.y);
    o.z = fmaf(sc, sum.z, bb.z);
    o.w = fmaf(sc, sum.w, bb.w);
    ((float4*)out)[(size_t)d * 16 + hl] = o;
}

// ---------------- launch ----------------
extern "C" void kernel_launch(void* const* d_in, const int* in_sizes, int n_in,
                              void* d_out, int out_size)
{
    const float* x  = (const float*)d_in[0];
    const int*   ei = (const int*)d_in[1];     // int32 (JAX coerces int64->int32)
    const float* W1 = (const float*)d_in[2];
    const float* b1 = (const float*)d_in[3];
    const float* W2 = (const float*)d_in[4];
    const float* b2 = (const float*)d_in[5];
    float* out = (float*)d_out;

    int n = in_sizes[0] / 128;   // 100000
    int E = in_sizes[1] / 2;     // 1600000
    const int* src = ei;
    const int* dst = ei + E;
    int nb = (n + SCAN_B - 1) / SCAN_B;

    cudaFuncSetAttribute(gemm_scale_kernel<128, false>, cudaFuncAttributeMaxDynamicSharedMemorySize, 98304);
    cudaFuncSetAttribute(gemm_scale_kernel<64, true>,   cudaFuncAttributeMaxDynamicSharedMemorySize, 65536);

    // graph structure (rebuilt every call: deterministic work)
    deg_init_kernel <<<(n + 255) / 256, 256>>>(n);
    deg_count_kernel<<<(E + 255) / 256, 256>>>(dst, E);
    scan1_kernel    <<<nb, SCAN_B>>>(n);
    scan2_kernel    <<<1, 128>>>(nb, n);
    scan3_kernel    <<<nb, SCAN_B>>>(n);
    fill_kernel     <<<(E + 255) / 256, 256>>>(src, dst, E);

    // layer 1
    gemm_scale_kernel<128, false><<<(n + 63) / 64, 256, 98304>>>(x, W1, n);
    agg1_kernel<<<(n * 32 + 255) / 256, 256>>>(b1, n);

    // layer 2
    gemm_scale_kernel<64, true><<<(n + 63) / 64, 256, 65536>>>(nullptr, W2, n);
    {
        int warps = (n + 1) / 2;
        agg2_kernel<<<(warps * 32 + 255) / 256, 256>>>(b2, out, n);
    }
}

// round 6
// speedup vs baseline: 1.6944x; 1.0869x over previous
#include <cuda_runtime.h>
#include <cuda_bf16.h>
#include <cuda_fp16.h>
#include <cstdint>

#define NNODES 100000
#define EMAX   1600000
#define KDIM   128
#define SCAN_B 1024

// ---------------- scratch (no allocation allowed) ----------------
__device__ __align__(16) float g_dinv[NNODES];
__device__            int   g_deg[NNODES];       // edge-only in-degree (no self loop)
__device__            int   g_off[NNODES + 1];   // CSR offsets
__device__            int   g_cur[NNODES];       // fill cursors
__device__            int   g_srcl[EMAX];        // CSR src lists (bucketed by dst)
__device__            int   g_bsum[128];
__device__            int   g_bpre[128];
__device__ __align__(16) __half g_tmp1h[(size_t)NNODES * 128]; // dinv*h in fp16 (layer1: 128, layer2: 64)
__device__ __align__(16) float  g_acc1[(size_t)NNODES * 128];  // relu'd layer1 output (N*128), fp32

// ---------------- degree ----------------
__global__ void deg_init_kernel(int n) {
    int i = blockIdx.x * blockDim.x + threadIdx.x;
    if (i < n) g_deg[i] = 0;
}

__global__ void deg_count_kernel(const int* __restrict__ dst, int E) {
    int i = blockIdx.x * blockDim.x + threadIdx.x;
    if (i < E) atomicAdd(&g_deg[dst[i]], 1);
}

// ---------------- multi-block exclusive scan ----------------
__global__ __launch_bounds__(SCAN_B) void scan1_kernel(int n) {
    __shared__ int sp[SCAN_B];
    int t = threadIdx.x;
    int i = blockIdx.x * SCAN_B + t;
    int d = (i < n) ? g_deg[i] : 0;
    if (i < n) g_dinv[i] = rsqrtf((float)d + 1.0f);   // +1 self loop
    sp[t] = d;
    __syncthreads();
#pragma unroll
    for (int off = 1; off < SCAN_B; off <<= 1) {
        int v = (t >= off) ? sp[t - off] : 0;
        __syncthreads();
        sp[t] += v;
        __syncthreads();
    }
    if (i < n) g_off[i] = sp[t] - d;      // exclusive within block
    if (t == SCAN_B - 1) g_bsum[blockIdx.x] = sp[t];
}

__global__ void scan2_kernel(int nb, int n) {
    __shared__ int sp[128];
    int t = threadIdx.x;
    int v = (t < nb) ? g_bsum[t] : 0;
    sp[t] = v;
    __syncthreads();
#pragma unroll
    for (int off = 1; off < 128; off <<= 1) {
        int u = (t >= off) ? sp[t - off] : 0;
        __syncthreads();
        sp[t] += u;
        __syncthreads();
    }
    if (t < nb) g_bpre[t] = sp[t] - v;    // exclusive
    if (t == nb - 1) g_off[n] = sp[t];    // grand total
}

__global__ __launch_bounds__(SCAN_B) void scan3_kernel(int n) {
    int i = blockIdx.x * SCAN_B + threadIdx.x;
    if (i < n) {
        g_off[i] += g_bpre[blockIdx.x];
        g_cur[i] = 0;
    }
}

// ---------------- CSR fill ----------------
__global__ void fill_kernel(const int* __restrict__ src,
                            const int* __restrict__ dst, int E) {
    int i = blockIdx.x * blockDim.x + threadIdx.x;
    if (i < E) {
        int d = dst[i];
        int pos = atomicAdd(&g_cur[d], 1);
        g_srcl[g_off[d] + pos] = src[i];
    }
}

// ---------------- GEMM with dinv-scaled epilogue (packed f32x2 FMA) --------
// writes g_tmp1h[r,:] = fp16( dinv[r] * (A[r,:] @ W) ),  A: [M,128], W: [128,NN]
// GIN: if true, A comes from g_acc1 (ignore Ap).
template<int NN, bool GIN>
__global__ __launch_bounds__(256) void gemm_scale_kernel(
        const float* __restrict__ Ap,
        const float* __restrict__ W, int M)
{
    constexpr int TN = NN / 32;     // 4 (NN=128) or 2 (NN=64)
    constexpr int BM = 64, TM = 8;
    extern __shared__ float sm[];
    float* Ws = sm;                 // KDIM*NN
    float* As = sm + KDIM * NN;     // BM*KDIM

    const float* A = GIN ? (const float*)g_acc1 : Ap;

    int tid = threadIdx.x;          // 256 threads
    for (int idx = tid; idx < KDIM * NN / 4; idx += 256)
        ((float4*)Ws)[idx] = ((const float4*)W)[idx];
    int m0 = blockIdx.x * BM;
    for (int idx = tid; idx < BM * (KDIM / 4); idx += 256) {
        int r = idx / (KDIM / 4);
        int c = idx % (KDIM / 4);
        float4 v = make_float4(0.f, 0.f, 0.f, 0.f);
        if (m0 + r < M) v = ((const float4*)(A + (size_t)(m0 + r) * KDIM))[c];
        ((float4*)(As + r * KDIM))[c] = v;
    }
    __syncthreads();

    int tx = tid & 31, ty = tid >> 5;
    unsigned long long acc[TM][TN / 2];
#pragma unroll
    for (int i = 0; i < TM; i++)
#pragma unroll
        for (int j = 0; j < TN / 2; j++) acc[i][j] = 0ull;

#pragma unroll 2
    for (int k = 0; k < KDIM; k += 4) {
        float4 a4[TM];
#pragma unroll
        for (int i = 0; i < TM; i++)
            a4[i] = *(const float4*)&As[(ty * TM + i) * KDIM + k];
#pragma unroll
        for (int kk = 0; kk < 4; kk++) {
            unsigned long long bp[TN / 2];
            if constexpr (TN == 4) {
                float4 bb = ((const float4*)(Ws + (k + kk) * NN))[tx];
                asm("mov.b64 %0, {%1,%2};" : "=l"(bp[0]) : "f"(bb.x), "f"(bb.y));
                asm("mov.b64 %0, {%1,%2};" : "=l"(bp[1]) : "f"(bb.z), "f"(bb.w));
            } else {
                float2 bb = ((const float2*)(Ws + (k + kk) * NN))[tx];
                asm("mov.b64 %0, {%1,%2};" : "=l"(bp[0]) : "f"(bb.x), "f"(bb.y));
            }
#pragma unroll
            for (int i = 0; i < TM; i++) {
                float av = (kk == 0) ? a4[i].x : (kk == 1) ? a4[i].y
                         : (kk == 2) ? a4[i].z : a4[i].w;
                unsigned long long a2;
                asm("mov.b64 %0, {%1,%1};" : "=l"(a2) : "f"(av));
#pragma unroll
                for (int j = 0; j < TN / 2; j++)
                    asm("fma.rn.f32x2 %0, %1, %2, %0;" : "+l"(acc[i][j]) : "l"(a2), "l"(bp[j]));
            }
        }
    }

#pragma unroll
    for (int i = 0; i < TM; i++) {
        int r = m0 + ty * TM + i;
        if (r < M) {
            float s = g_dinv[r];
            float v[4];
            asm("mov.b64 {%0,%1}, %2;" : "=f"(v[0]), "=f"(v[1]) : "l"(acc[i][0]));
            if constexpr (TN == 4) {
                asm("mov.b64 {%0,%1}, %2;" : "=f"(v[2]), "=f"(v[3]) : "l"(acc[i][1]));
                __half2 p0 = __floats2half2_rn(v[0] * s, v[1] * s);
                __half2 p1 = __floats2half2_rn(v[2] * s, v[3] * s);
                uint2 u;
                u.x = *(unsigned*)&p0;
                u.y = *(unsigned*)&p1;
                *(uint2*)(g_tmp1h + (size_t)r * NN + 4 * tx) = u;
            } else {
                __half2 p0 = __floats2half2_rn(v[0] * s, v[1] * s);
                *(unsigned*)(g_tmp1h + (size_t)r * NN + 2 * tx) = *(unsigned*)&p0;
            }
        }
    }
}

// ---------------- gather aggregation (fp16 rows, fp32 accumulate) ----------
__device__ __forceinline__ void acc_u2(float4& sum, uint2 u) {
    __half2 h0 = *(__half2*)&u.x;
    __half2 h1 = *(__half2*)&u.y;
    float2 f0 = __half22float2(h0);
    float2 f1 = __half22float2(h1);
    sum.x += f0.x; sum.y += f0.y; sum.z += f1.x; sum.w += f1.y;
}

// layer 1: one warp per node; row = 128 halves = 32 uint2; lane covers cols 4*lane..4*lane+3
__global__ void agg1_kernel(const float* __restrict__ b1, int n) {
    int w = (int)((blockIdx.x * (unsigned)blockDim.x + threadIdx.x) >> 5);
    int lane = threadIdx.x & 31;
    if (w >= n) return;
    const uint2* base = (const uint2*)g_tmp1h;
    float4 sum = make_float4(0.f, 0.f, 0.f, 0.f);
    acc_u2(sum, base[(size_t)w * 32 + lane]);   // self loop
    int j = g_off[w], end = g_off[w + 1];
    for (; j + 4 <= end; j += 4) {
        int s0 = g_srcl[j], s1 = g_srcl[j + 1], s2 = g_srcl[j + 2], s3 = g_srcl[j + 3];
        uint2 u0 = base[(size_t)s0 * 32 + lane];
        uint2 u1 = base[(size_t)s1 * 32 + lane];
        uint2 u2 = base[(size_t)s2 * 32 + lane];
        uint2 u3 = base[(size_t)s3 * 32 + lane];
        acc_u2(sum, u0); acc_u2(sum, u1); acc_u2(sum, u2); acc_u2(sum, u3);
    }
    for (; j < end; j++) {
        int s = g_srcl[j];
        acc_u2(sum, base[(size_t)s * 32 + lane]);
    }
    float sc = g_dinv[w];
    float4 bb = ((const float4*)b1)[lane];
    float4 o;
    o.x = fmaxf(fmaf(sc, sum.x, bb.x), 0.f);
    o.y = fmaxf(fmaf(sc, sum.y, bb.y), 0.f);
    o.z = fmaxf(fmaf(sc, sum.z, bb.z), 0.f);
    o.w = fmaxf(fmaf(sc, sum.w, bb.w), 0.f);
    ((float4*)g_acc1)[(size_t)w * 32 + lane] = o;
}

// layer 2: two nodes per warp; row = 64 halves = 16 uint2; half-lane covers cols 4*hl..4*hl+3
__global__ void agg2_kernel(const float* __restrict__ b2, float* __restrict__ out, int n) {
    int w = (int)((blockIdx.x * (unsigned)blockDim.x + threadIdx.x) >> 5);
    int lane = threadIdx.x & 31;
    int d = w * 2 + (lane >> 4);
    int hl = lane & 15;
    if (d >= n) return;
    const uint2* base = (const uint2*)g_tmp1h;
    float4 sum = make_float4(0.f, 0.f, 0.f, 0.f);
    acc_u2(sum, base[(size_t)d * 16 + hl]);     // self loop
    int j = g_off[d], end = g_off[d + 1];
    for (; j + 4 <= end; j += 4) {
        int s0 = g_srcl[j], s1 = g_srcl[j + 1], s2 = g_srcl[j + 2], s3 = g_srcl[j + 3];
        uint2 u0 = base[(size_t)s0 * 16 + hl];
        uint2 u1 = base[(size_t)s1 * 16 + hl];
        uint2 u2 = base[(size_t)s2 * 16 + hl];
        uint2 u3 = base[(size_t)s3 * 16 + hl];
        acc_u2(sum, u0); acc_u2(sum, u1); acc_u2(sum, u2); acc_u2(sum, u3);
    }
    for (; j < end; j++) {
        int s = g_srcl[j];
        acc_u2(sum, base[(size_t)s * 16 + hl]);
    }
    float sc = g_dinv[d];
    float4 bb = ((const float4*)b2)[hl];
    float4 o;
    o.x = fmaf(sc, sum.x, bb.x);
    o.y = fmaf(sc, sum.y, bb.y);
    o.z = fmaf(sc, sum.z, bb.z);
    o.w = fmaf(sc, sum.w, bb.w);
    ((float4*)out)[(size_t)d * 16 + hl] = o;
}

// ---------------- launch ----------------
extern "C" void kernel_launch(void* const* d_in, const int* in_sizes, int n_in,
                              void* d_out, int out_size)
{
    const float* x  = (const float*)d_in[0];
    const int*   ei = (const int*)d_in[1];     // int32 (JAX coerces int64->int32)
    const float* W1 = (const float*)d_in[2];
    const float* b1 = (const float*)d_in[3];
    const float* W2 = (const float*)d_in[4];
    const float* b2 = (const float*)d_in[5];
    float* out = (float*)d_out;

    int n = in_sizes[0] / 128;   // 100000
    int E = in_sizes[1] / 2;     // 1600000
    const int* src = ei;
    const int* dst = ei + E;
    int nb = (n + SCAN_B - 1) / SCAN_B;

    cudaFuncSetAttribute(gemm_scale_kernel<128, false>, cudaFuncAttributeMaxDynamicSharedMemorySize, 98304);
    cudaFuncSetAttribute(gemm_scale_kernel<64, true>,   cudaFuncAttributeMaxDynamicSharedMemorySize, 65536);

    // graph structure (rebuilt every call: deterministic work)
    deg_init_kernel <<<(n + 255) / 256, 256>>>(n);
    deg_count_kernel<<<(E + 255) / 256, 256>>>(dst, E);
    scan1_kernel    <<<nb, SCAN_B>>>(n);
    scan2_kernel    <<<1, 128>>>(nb, n);
    scan3_kernel    <<<nb, SCAN_B>>>(n);
    fill_kernel     <<<(E + 255) / 256, 256>>>(src, dst, E);

    // layer 1
    gemm_scale_kernel<128, false><<<(n + 63) / 64, 256, 98304>>>(x, W1, n);
    agg1_kernel<<<(n * 32 + 255) / 256, 256>>>(b1, n);

    // layer 2
    gemm_scale_kernel<64, true><<<(n + 63) / 64, 256, 65536>>>(nullptr, W2, n);
    {
        int warps = (n + 1) / 2;
        agg2_kernel<<<(warps * 32 + 255) / 256, 256>>>(b2, out, n);
    }
}

// round 10
// speedup vs baseline: 1.9449x; 1.1478x over previous
#include <cuda_runtime.h>
#include <cuda_bf16.h>
#include <cuda_fp16.h>
#include <mma.h>
#include <cstdint>

using namespace nvcuda;

#define NNODES 100000
#define EMAX   1600000
#define KDIM   128
#define SCAN_B 1024

// ---------------- scratch (no allocation allowed) ----------------
__device__ __align__(16) float g_dinv[NNODES];
__device__            int   g_deg[NNODES];
__device__            int   g_off[NNODES + 1];
__device__            int   g_cur[NNODES];
__device__            int   g_srcl[EMAX];
__device__            int   g_bsum[128];
__device__            int   g_bpre[128];
__device__ __align__(16) __half g_tmp1h[(size_t)NNODES * 128];  // GEMM out (dinv*h), fp16
__device__ __align__(16) __half g_hacth[(size_t)NNODES * 128];  // relu(layer1) fp16 = GEMM2's A

// ---------------- degree ----------------
__global__ void deg_init_kernel(int n) {
    int i = blockIdx.x * blockDim.x + threadIdx.x;
    if (i < n) g_deg[i] = 0;
}
__global__ void deg_count_kernel(const int* __restrict__ dst, int E) {
    int i = blockIdx.x * blockDim.x + threadIdx.x;
    if (i < E) atomicAdd(&g_deg[dst[i]], 1);
}

// ---------------- multi-block exclusive scan ----------------
__global__ __launch_bounds__(SCAN_B) void scan1_kernel(int n) {
    __shared__ int sp[SCAN_B];
    int t = threadIdx.x;
    int i = blockIdx.x * SCAN_B + t;
    int d = (i < n) ? g_deg[i] : 0;
    if (i < n) g_dinv[i] = rsqrtf((float)d + 1.0f);
    sp[t] = d;
    __syncthreads();
#pragma unroll
    for (int off = 1; off < SCAN_B; off <<= 1) {
        int v = (t >= off) ? sp[t - off] : 0;
        __syncthreads();
        sp[t] += v;
        __syncthreads();
    }
    if (i < n) g_off[i] = sp[t] - d;
    if (t == SCAN_B - 1) g_bsum[blockIdx.x] = sp[t];
}
__global__ void scan2_kernel(int nb, int n) {
    __shared__ int sp[128];
    int t = threadIdx.x;
    int v = (t < nb) ? g_bsum[t] : 0;
    sp[t] = v;
    __syncthreads();
#pragma unroll
    for (int off = 1; off < 128; off <<= 1) {
        int u = (t >= off) ? sp[t - off] : 0;
        __syncthreads();
        sp[t] += u;
        __syncthreads();
    }
    if (t < nb) g_bpre[t] = sp[t] - v;
    if (t == nb - 1) g_off[n] = sp[t];
}
__global__ __launch_bounds__(SCAN_B) void scan3_kernel(int n) {
    int i = blockIdx.x * SCAN_B + threadIdx.x;
    if (i < n) {
        g_off[i] += g_bpre[blockIdx.x];
        g_cur[i] = 0;
    }
}

// ---------------- CSR fill ----------------
__global__ void fill_kernel(const int* __restrict__ src,
                            const int* __restrict__ dst, int E) {
    int i = blockIdx.x * blockDim.x + threadIdx.x;
    if (i < E) {
        int d = dst[i];
        int pos = atomicAdd(&g_cur[d], 1);
        g_srcl[g_off[d] + pos] = src[i];
    }
}

// ---------------- WMMA GEMM, dinv-scaled fp16 epilogue ----------------
// g_tmp1h[r, 0:BN] = fp16( dinv[r] * (A[r,:] @ W) ),  A: [M,128], W: [128,BN] fp32
// AHALF: A = g_hacth (fp16), else A = Aptr (fp32).
template<int BN, bool AHALF>
__global__ __launch_bounds__(256) void wmma_gemm_kernel(
        const float* __restrict__ Aptr, const float* __restrict__ W, int M)
{
    constexpr int AS = 136;            // A smem stride (halves)
    constexpr int BS = BN + 8;         // W smem stride (halves)
    constexpr int CS = BN + 8;         // C smem stride (floats)
    constexpr int NF = BN / 32;        // 16-wide n-frags per warp (warp covers BN/2)
    extern __shared__ __half smh[];
    __half* Asm = smh;                 // 128 x AS halves
    __half* Wsm = smh + 128 * AS;      // 128 x BS halves
    float*  Csm = (float*)smh;         // 128 x CS floats (aliases A/W after mma)

    int tid = threadIdx.x;
    int warp = tid >> 5;
    int wm = (warp >> 1) * 32;         // 4 m-warps x 32 rows
    int wn = (warp & 1) * (BN / 2);    // 2 n-warps x BN/2 cols
    int m0 = blockIdx.x * 128;

    // ---- stage A tile (fp16), zero-pad OOB rows ----
    if constexpr (AHALF) {
        const __half* Ah = g_hacth;
        for (int idx = tid; idx < 128 * 16; idx += 256) {   // 16 x uint4 (8 halves) per row
            int r = idx >> 4, c8 = (idx & 15) * 8;
            uint4 u = make_uint4(0u, 0u, 0u, 0u);
            if (m0 + r < M) u = *(const uint4*)(Ah + (size_t)(m0 + r) * 128 + c8);
            *(uint4*)(Asm + r * AS + c8) = u;
        }
    } else {
        for (int idx = tid; idx < 128 * 32; idx += 256) {   // 32 x float4 (4 floats) per row
            int r = idx >> 5, c4 = (idx & 31) * 4;
            float4 v = make_float4(0.f, 0.f, 0.f, 0.f);
            if (m0 + r < M) v = *(const float4*)(Aptr + (size_t)(m0 + r) * 128 + c4);
            __half2 p0 = __floats2half2_rn(v.x, v.y);
            __half2 p1 = __floats2half2_rn(v.z, v.w);
            uint2 u; u.x = *(unsigned*)&p0; u.y = *(unsigned*)&p1;
            *(uint2*)(Asm + r * AS + c4) = u;
        }
    }
    // ---- stage W (fp32 -> fp16): 4 halves per step ----
    for (int idx = tid; idx < 128 * (BN / 4); idx += 256) {
        int r = idx / (BN / 4), c4 = (idx % (BN / 4)) * 4;
        float4 v = *(const float4*)(W + (size_t)r * BN + c4);
        __half2 p0 = __floats2half2_rn(v.x, v.y);
        __half2 p1 = __floats2half2_rn(v.z, v.w);
        uint2 u; u.x = *(unsigned*)&p0; u.y = *(unsigned*)&p1;
        *(uint2*)(Wsm + r * BS + c4) = u;
    }
    __syncthreads();

    wmma::fragment<wmma::accumulator, 16, 16, 16, float> c[2][NF];
#pragma unroll
    for (int i = 0; i < 2; i++)
#pragma unroll
        for (int j = 0; j < NF; j++) wmma::fill_fragment(c[i][j], 0.0f);

#pragma unroll
    for (int k = 0; k < 128; k += 16) {
        wmma::fragment<wmma::matrix_a, 16, 16, 16, __half, wmma::row_major> a[2];
#pragma unroll
        for (int i = 0; i < 2; i++)
            wmma::load_matrix_sync(a[i], Asm + (wm + i * 16) * AS + k, AS);
#pragma unroll
        for (int j = 0; j < NF; j++) {
            wmma::fragment<wmma::matrix_b, 16, 16, 16, __half, wmma::row_major> b;
            wmma::load_matrix_sync(b, Wsm + k * BS + wn + j * 16, BS);
#pragma unroll
            for (int i = 0; i < 2; i++)
                wmma::mma_sync(c[i][j], a[i], b, c[i][j]);
        }
    }

    __syncthreads();    // A/W staging dead; reuse as C staging
#pragma unroll
    for (int i = 0; i < 2; i++)
#pragma unroll
        for (int j = 0; j < NF; j++)
            wmma::store_matrix_sync(Csm + (wm + i * 16) * CS + wn + j * 16,
                                    c[i][j], CS, wmma::mem_row_major);
    __syncthreads();

    // ---- epilogue: dinv scale, pack fp16, store ----
    for (int idx = tid; idx < 128 * (BN / 2); idx += 256) {
        int r = idx / (BN / 2), c2 = (idx % (BN / 2)) * 2;
        int gr = m0 + r;
        if (gr < M) {
            float s = g_dinv[gr];
            float2 v = *(float2*)(Csm + r * CS + c2);
            __half2 h = __floats2half2_rn(v.x * s, v.y * s);
            *(unsigned*)(g_tmp1h + (size_t)gr * BN + c2) = *(unsigned*)&h;
        }
    }
}

// ---------------- gather aggregation (fp16 rows, fp32 accumulate) ----------
__device__ __forceinline__ void acc_u2(float4& sum, uint2 u) {
    __half2 h0 = *(__half2*)&u.x;
    __half2 h1 = *(__half2*)&u.y;
    float2 f0 = __half22float2(h0);
    float2 f1 = __half22float2(h1);
    sum.x += f0.x; sum.y += f0.y; sum.z += f1.x; sum.w += f1.y;
}

// layer 1: one warp per node; writes fp16 hact
__global__ void agg1_kernel(const float* __restrict__ b1, int n) {
    int w = (int)((blockIdx.x * (unsigned)blockDim.x + threadIdx.x) >> 5);
    int lane = threadIdx.x & 31;
    if (w >= n) return;
    const uint2* base = (const uint2*)g_tmp1h;
    float4 sum = make_float4(0.f, 0.f, 0.f, 0.f);
    acc_u2(sum, base[(size_t)w * 32 + lane]);   // self loop
    int j = g_off[w], end = g_off[w + 1];
    for (; j + 4 <= end; j += 4) {
        int s0 = g_srcl[j], s1 = g_srcl[j + 1], s2 = g_srcl[j + 2], s3 = g_srcl[j + 3];
        uint2 u0 = base[(size_t)s0 * 32 + lane];
        uint2 u1 = base[(size_t)s1 * 32 + lane];
        uint2 u2 = base[(size_t)s2 * 32 + lane];
        uint2 u3 = base[(size_t)s3 * 32 + lane];
        acc_u2(sum, u0); acc_u2(sum, u1); acc_u2(sum, u2); acc_u2(sum, u3);
    }
    for (; j < end; j++) acc_u2(sum, base[(size_t)g_srcl[j] * 32 + lane]);
    float sc = g_dinv[w];
    float4 bb = ((const float4*)b1)[lane];
    float ox = fmaxf(fmaf(sc, sum.x, bb.x), 0.f);
    float oy = fmaxf(fmaf(sc, sum.y, bb.y), 0.f);
    float oz = fmaxf(fmaf(sc, sum.z, bb.z), 0.f);
    float ow = fmaxf(fmaf(sc, sum.w, bb.w), 0.f);
    __half2 p0 = __floats2half2_rn(ox, oy);
    __half2 p1 = __floats2half2_rn(oz, ow);
    uint2 u; u.x = *(unsigned*)&p0; u.y = *(unsigned*)&p1;
    ((uint2*)g_hacth)[(size_t)w * 32 + lane] = u;
}

// layer 2: two nodes per warp; fp32 output
__global__ void agg2_kernel(const float* __restrict__ b2, float* __restrict__ out, int n) {
    int w = (int)((blockIdx.x * (unsigned)blockDim.x + threadIdx.x) >> 5);
    int lane = threadIdx.x & 31;
    int d = w * 2 + (lane >> 4);
    int hl = lane & 15;
    if (d >= n) return;
    const uint2* base = (const uint2*)g_tmp1h;
    float4 sum = make_float4(0.f, 0.f, 0.f, 0.f);
    acc_u2(sum, base[(size_t)d * 16 + hl]);     // self loop
    int j = g_off[d], end = g_off[d + 1];
    for (; j + 4 <= end; j += 4) {
        int s0 = g_srcl[j], s1 = g_srcl[j + 1], s2 = g_srcl[j + 2], s3 = g_srcl[j + 3];
        uint2 u0 = base[(size_t)s0 * 16 + hl];
        uint2 u1 = base[(size_t)s1 * 16 + hl];
        uint2 u2 = base[(size_t)s2 * 16 + hl];
        uint2 u3 = base[(size_t)s3 * 16 + hl];
        acc_u2(sum, u0); acc_u2(sum, u1); acc_u2(sum, u2); acc_u2(sum, u3);
    }
    for (; j < end; j++) acc_u2(sum, base[(size_t)g_srcl[j] * 16 + hl]);
    float sc = g_dinv[d];
    float4 bb = ((const float4*)b2)[hl];
    float4 o;
    o.x = fmaf(sc, sum.x, bb.x);
    o.y = fmaf(sc, sum.y, bb.y);
    o.z = fmaf(sc, sum.z, bb.z);
    o.w = fmaf(sc, sum.w, bb.w);
    ((float4*)out)[(size_t)d * 16 + hl] = o;
}

// ---------------- launch ----------------
extern "C" void kernel_launch(void* const* d_in, const int* in_sizes, int n_in,
                              void* d_out, int out_size)
{
    const float* x  = (const float*)d_in[0];
    const int*   ei = (const int*)d_in[1];     // int32 (JAX coerces int64->int32)
    const float* W1 = (const float*)d_in[2];
    const float* b1 = (const float*)d_in[3];
    const float* W2 = (const float*)d_in[4];
    const float* b2 = (const float*)d_in[5];
    float* out = (float*)d_out;

    int n = in_sizes[0] / 128;   // 100000
    int E = in_sizes[1] / 2;     // 1600000
    const int* src = ei;
    const int* dst = ei + E;
    int nb = (n + SCAN_B - 1) / SCAN_B;

    // smem: BN=128: halves stage = (128*136+128*136)*2 = 69632, C stage = 128*136*4 = 69632
    //       BN=64:  halves stage = (128*136+128*72)*2  = 53248, C stage = 128*72*4  = 36864
    constexpr int SM1 = 69632;
    constexpr int SM2 = 53248;
    cudaFuncSetAttribute(wmma_gemm_kernel<128, false>, cudaFuncAttributeMaxDynamicSharedMemorySize, SM1);
    cudaFuncSetAttribute(wmma_gemm_kernel<64, true>,   cudaFuncAttributeMaxDynamicSharedMemorySize, SM2);

    // graph structure
    deg_init_kernel <<<(n + 255) / 256, 256>>>(n);
    deg_count_kernel<<<(E + 255) / 256, 256>>>(dst, E);
    scan1_kernel    <<<nb, SCAN_B>>>(n);
    scan2_kernel    <<<1, 128>>>(nb, n);
    scan3_kernel    <<<nb, SCAN_B>>>(n);
    fill_kernel     <<<(E + 255) / 256, 256>>>(src, dst, E);

    // layer 1
    wmma_gemm_kernel<128, false><<<(n + 127) / 128, 256, SM1>>>(x, W1, n);
    agg1_kernel<<<(n * 32 + 255) / 256, 256>>>(b1, n);

    // layer 2
    wmma_gemm_kernel<64, true><<<(n + 127) / 128, 256, SM2>>>(nullptr, W2, n);
    {
        int warps = (n + 1) / 2;
        agg2_kernel<<<(warps * 32 + 255) / 256, 256>>>(b2, out, n);
    }
}

// round 11
// speedup vs baseline: 1.9624x; 1.0090x over previous
#include <cuda_runtime.h>
#include <cuda_bf16.h>
#include <cuda_fp16.h>
#include <mma.h>
#include <cstdint>

using namespace nvcuda;

#define NNODES 100000
#define EMAX   1600000
#define KDIM   128
#define SCAN_B 1024

// ---------------- scratch (no allocation allowed) ----------------
__device__ __align__(16) float g_dinv[NNODES];
__device__            int   g_deg[NNODES];
__device__            int   g_off[NNODES + 1];
__device__            int   g_cur[NNODES];
__device__            int   g_srcl[EMAX];
__device__            int   g_bsum[128];
__device__            int   g_bpre[128];
__device__ __align__(16) __half g_tmp1h[(size_t)NNODES * 128];  // GEMM out (dinv*h), fp16
__device__ __align__(16) __half g_hacth[(size_t)NNODES * 128];  // relu(layer1) fp16 = GEMM2's A

// ---------------- degree ----------------
__global__ void deg_init_kernel(int n) {
    int i = blockIdx.x * blockDim.x + threadIdx.x;
    if (i < n) g_deg[i] = 0;
}
// 4 edges per thread via int4
__global__ void deg_count_kernel(const int* __restrict__ dst, int E) {
    int i4 = blockIdx.x * blockDim.x + threadIdx.x;
    int i = i4 * 4;
    if (i + 4 <= E) {
        int4 d = *(const int4*)(dst + i);
        atomicAdd(&g_deg[d.x], 1);
        atomicAdd(&g_deg[d.y], 1);
        atomicAdd(&g_deg[d.z], 1);
        atomicAdd(&g_deg[d.w], 1);
    } else {
        for (; i < E; i++) atomicAdd(&g_deg[dst[i]], 1);
    }
}

// ---------------- multi-block exclusive scan ----------------
__global__ __launch_bounds__(SCAN_B) void scan1_kernel(int n) {
    __shared__ int sp[SCAN_B];
    int t = threadIdx.x;
    int i = blockIdx.x * SCAN_B + t;
    int d = (i < n) ? g_deg[i] : 0;
    if (i < n) g_dinv[i] = rsqrtf((float)d + 1.0f);
    sp[t] = d;
    __syncthreads();
#pragma unroll
    for (int off = 1; off < SCAN_B; off <<= 1) {
        int v = (t >= off) ? sp[t - off] : 0;
        __syncthreads();
        sp[t] += v;
        __syncthreads();
    }
    if (i < n) g_off[i] = sp[t] - d;
    if (t == SCAN_B - 1) g_bsum[blockIdx.x] = sp[t];
}
__global__ void scan2_kernel(int nb, int n) {
    __shared__ int sp[128];
    int t = threadIdx.x;
    int v = (t < nb) ? g_bsum[t] : 0;
    sp[t] = v;
    __syncthreads();
#pragma unroll
    for (int off = 1; off < 128; off <<= 1) {
        int u = (t >= off) ? sp[t - off] : 0;
        __syncthreads();
        sp[t] += u;
        __syncthreads();
    }
    if (t < nb) g_bpre[t] = sp[t] - v;
    if (t == nb - 1) g_off[n] = sp[t];
}
__global__ __launch_bounds__(SCAN_B) void scan3_kernel(int n) {
    int i = blockIdx.x * SCAN_B + threadIdx.x;
    if (i < n) {
        g_off[i] += g_bpre[blockIdx.x];
        g_cur[i] = 0;
    }
}

// ---------------- CSR fill ----------------
__global__ void fill_kernel(const int* __restrict__ src,
                            const int* __restrict__ dst, int E) {
    int i = blockIdx.x * blockDim.x + threadIdx.x;
    if (i < E) {
        int d = dst[i];
        int pos = atomicAdd(&g_cur[d], 1);
        g_srcl[g_off[d] + pos] = src[i];
    }
}

// ---------------- WMMA GEMM, dinv-scaled fp16 epilogue ----------------
// g_tmp1h[r, 0:BN] = fp16( dinv[r] * (A[r,:] @ W) ),  A: [M,128], W: [128,BN] fp32
template<int BN, bool AHALF>
__global__ __launch_bounds__(256) void wmma_gemm_kernel(
        const float* __restrict__ Aptr, const float* __restrict__ W, int M)
{
    constexpr int AS = 136;
    constexpr int BS = BN + 8;
    constexpr int CS = BN + 8;
    constexpr int NF = BN / 32;
    extern __shared__ __half smh[];
    __half* Asm = smh;
    __half* Wsm = smh + 128 * AS;
    float*  Csm = (float*)smh;

    int tid = threadIdx.x;
    int warp = tid >> 5;
    int wm = (warp >> 1) * 32;
    int wn = (warp & 1) * (BN / 2);
    int m0 = blockIdx.x * 128;

    if constexpr (AHALF) {
        const __half* Ah = g_hacth;
        for (int idx = tid; idx < 128 * 16; idx += 256) {
            int r = idx >> 4, c8 = (idx & 15) * 8;
            uint4 u = make_uint4(0u, 0u, 0u, 0u);
            if (m0 + r < M) u = *(const uint4*)(Ah + (size_t)(m0 + r) * 128 + c8);
            *(uint4*)(Asm + r * AS + c8) = u;
        }
    } else {
        for (int idx = tid; idx < 128 * 32; idx += 256) {
            int r = idx >> 5, c4 = (idx & 31) * 4;
            float4 v = make_float4(0.f, 0.f, 0.f, 0.f);
            if (m0 + r < M) v = *(const float4*)(Aptr + (size_t)(m0 + r) * 128 + c4);
            __half2 p0 = __floats2half2_rn(v.x, v.y);
            __half2 p1 = __floats2half2_rn(v.z, v.w);
            uint2 u; u.x = *(unsigned*)&p0; u.y = *(unsigned*)&p1;
            *(uint2*)(Asm + r * AS + c4) = u;
        }
    }
    for (int idx = tid; idx < 128 * (BN / 4); idx += 256) {
        int r = idx / (BN / 4), c4 = (idx % (BN / 4)) * 4;
        float4 v = *(const float4*)(W + (size_t)r * BN + c4);
        __half2 p0 = __floats2half2_rn(v.x, v.y);
        __half2 p1 = __floats2half2_rn(v.z, v.w);
        uint2 u; u.x = *(unsigned*)&p0; u.y = *(unsigned*)&p1;
        *(uint2*)(Wsm + r * BS + c4) = u;
    }
    __syncthreads();

    wmma::fragment<wmma::accumulator, 16, 16, 16, float> c[2][NF];
#pragma unroll
    for (int i = 0; i < 2; i++)
#pragma unroll
        for (int j = 0; j < NF; j++) wmma::fill_fragment(c[i][j], 0.0f);

#pragma unroll
    for (int k = 0; k < 128; k += 16) {
        wmma::fragment<wmma::matrix_a, 16, 16, 16, __half, wmma::row_major> a[2];
#pragma unroll
        for (int i = 0; i < 2; i++)
            wmma::load_matrix_sync(a[i], Asm + (wm + i * 16) * AS + k, AS);
#pragma unroll
        for (int j = 0; j < NF; j++) {
            wmma::fragment<wmma::matrix_b, 16, 16, 16, __half, wmma::row_major> b;
            wmma::load_matrix_sync(b, Wsm + k * BS + wn + j * 16, BS);
#pragma unroll
            for (int i = 0; i < 2; i++)
                wmma::mma_sync(c[i][j], a[i], b, c[i][j]);
        }
    }

    __syncthreads();
#pragma unroll
    for (int i = 0; i < 2; i++)
#pragma unroll
        for (int j = 0; j < NF; j++)
            wmma::store_matrix_sync(Csm + (wm + i * 16) * CS + wn + j * 16,
                                    c[i][j], CS, wmma::mem_row_major);
    __syncthreads();

    for (int idx = tid; idx < 128 * (BN / 2); idx += 256) {
        int r = idx / (BN / 2), c2 = (idx % (BN / 2)) * 2;
        int gr = m0 + r;
        if (gr < M) {
            float s = g_dinv[gr];
            float2 v = *(float2*)(Csm + r * CS + c2);
            __half2 h = __floats2half2_rn(v.x * s, v.y * s);
            *(unsigned*)(g_tmp1h + (size_t)gr * BN + c2) = *(unsigned*)&h;
        }
    }
}

// ---------------- gather aggregation (uint4 = 8 halves per lane) ----------
__device__ __forceinline__ void acc_u4(float* s, uint4 u) {
    __half2* h = (__half2*)&u;
#pragma unroll
    for (int i = 0; i < 4; i++) {
        float2 f = __half22float2(h[i]);
        s[2 * i]     += f.x;
        s[2 * i + 1] += f.y;
    }
}

// layer 1: 2 nodes per warp, 16 lanes/node, 8 cols/lane; writes fp16 hact
__global__ void agg1_kernel(const float* __restrict__ b1, int n) {
    int w = (int)((blockIdx.x * (unsigned)blockDim.x + threadIdx.x) >> 5);
    int lane = threadIdx.x & 31;
    int d = w * 2 + (lane >> 4);
    int hl = lane & 15;              // 16 x uint4 per 128-half row
    if (d >= n) return;
    const uint4* base = (const uint4*)g_tmp1h;
    float s[8] = {0, 0, 0, 0, 0, 0, 0, 0};
    acc_u4(s, base[(size_t)d * 16 + hl]);       // self loop
    int j = g_off[d], end = g_off[d + 1];
    for (; j + 4 <= end; j += 4) {
        int s0 = g_srcl[j], s1 = g_srcl[j + 1], s2 = g_srcl[j + 2], s3 = g_srcl[j + 3];
        uint4 u0 = base[(size_t)s0 * 16 + hl];
        uint4 u1 = base[(size_t)s1 * 16 + hl];
        uint4 u2 = base[(size_t)s2 * 16 + hl];
        uint4 u3 = base[(size_t)s3 * 16 + hl];
        acc_u4(s, u0); acc_u4(s, u1); acc_u4(s, u2); acc_u4(s, u3);
    }
    for (; j < end; j++) acc_u4(s, base[(size_t)g_srcl[j] * 16 + hl]);
    float sc = g_dinv[d];
    float4 ba = ((const float4*)b1)[hl * 2];
    float4 bbv = ((const float4*)b1)[hl * 2 + 1];
    float o[8];
    o[0] = fmaxf(fmaf(sc, s[0], ba.x), 0.f);
    o[1] = fmaxf(fmaf(sc, s[1], ba.y), 0.f);
    o[2] = fmaxf(fmaf(sc, s[2], ba.z), 0.f);
    o[3] = fmaxf(fmaf(sc, s[3], ba.w), 0.f);
    o[4] = fmaxf(fmaf(sc, s[4], bbv.x), 0.f);
    o[5] = fmaxf(fmaf(sc, s[5], bbv.y), 0.f);
    o[6] = fmaxf(fmaf(sc, s[6], bbv.z), 0.f);
    o[7] = fmaxf(fmaf(sc, s[7], bbv.w), 0.f);
    __half2 p0 = __floats2half2_rn(o[0], o[1]);
    __half2 p1 = __floats2half2_rn(o[2], o[3]);
    __half2 p2 = __floats2half2_rn(o[4], o[5]);
    __half2 p3 = __floats2half2_rn(o[6], o[7]);
    uint4 u;
    u.x = *(unsigned*)&p0; u.y = *(unsigned*)&p1;
    u.z = *(unsigned*)&p2; u.w = *(unsigned*)&p3;
    ((uint4*)g_hacth)[(size_t)d * 16 + hl] = u;
}

// layer 2: 4 nodes per warp, 8 lanes/node, 8 cols/lane; fp32 output
__global__ void agg2_kernel(const float* __restrict__ b2, float* __restrict__ out, int n) {
    int w = (int)((blockIdx.x * (unsigned)blockDim.x + threadIdx.x) >> 5);
    int lane = threadIdx.x & 31;
    int d = w * 4 + (lane >> 3);
    int hl = lane & 7;               // 8 x uint4 per 64-half row
    if (d >= n) return;
    const uint4* base = (const uint4*)g_tmp1h;
    float s[8] = {0, 0, 0, 0, 0, 0, 0, 0};
    acc_u4(s, base[(size_t)d * 8 + hl]);        // self loop
    int j = g_off[d], end = g_off[d + 1];
    for (; j + 4 <= end; j += 4) {
        int s0 = g_srcl[j], s1 = g_srcl[j + 1], s2 = g_srcl[j + 2], s3 = g_srcl[j + 3];
        uint4 u0 = base[(size_t)s0 * 8 + hl];
        uint4 u1 = base[(size_t)s1 * 8 + hl];
        uint4 u2 = base[(size_t)s2 * 8 + hl];
        uint4 u3 = base[(size_t)s3 * 8 + hl];
        acc_u4(s, u0); acc_u4(s, u1); acc_u4(s, u2); acc_u4(s, u3);
    }
    for (; j < end; j++) acc_u4(s, base[(size_t)g_srcl[j] * 8 + hl]);
    float sc = g_dinv[d];
    float4 ba = ((const float4*)b2)[hl * 2];
    float4 bbv = ((const float4*)b2)[hl * 2 + 1];
    float4 o0, o1;
    o0.x = fmaf(sc, s[0], ba.x);
    o0.y = fmaf(sc, s[1], ba.y);
    o0.z = fmaf(sc, s[2], ba.z);
    o0.w = fmaf(sc, s[3], ba.w);
    o1.x = fmaf(sc, s[4], bbv.x);
    o1.y = fmaf(sc, s[5], bbv.y);
    o1.z = fmaf(sc, s[6], bbv.z);
    o1.w = fmaf(sc, s[7], bbv.w);
    float4* op = (float4*)(out + (size_t)d * 64 + hl * 8);
    op[0] = o0;
    op[1] = o1;
}

// ---------------- launch ----------------
extern "C" void kernel_launch(void* const* d_in, const int* in_sizes, int n_in,
                              void* d_out, int out_size)
{
    const float* x  = (const float*)d_in[0];
    const int*   ei = (const int*)d_in[1];     // int32 (JAX coerces int64->int32)
    const float* W1 = (const float*)d_in[2];
    const float* b1 = (const float*)d_in[3];
    const float* W2 = (const float*)d_in[4];
    const float* b2 = (const float*)d_in[5];
    float* out = (float*)d_out;

    int n = in_sizes[0] / 128;   // 100000
    int E = in_sizes[1] / 2;     // 1600000
    const int* src = ei;
    const int* dst = ei + E;
    int nb = (n + SCAN_B - 1) / SCAN_B;

    constexpr int SM1 = 69632;
    constexpr int SM2 = 53248;
    cudaFuncSetAttribute(wmma_gemm_kernel<128, false>, cudaFuncAttributeMaxDynamicSharedMemorySize, SM1);
    cudaFuncSetAttribute(wmma_gemm_kernel<64, true>,   cudaFuncAttributeMaxDynamicSharedMemorySize, SM2);

    // graph structure
    deg_init_kernel <<<(n + 255) / 256, 256>>>(n);
    {
        int t4 = (E + 3) / 4;
        deg_count_kernel<<<(t4 + 255) / 256, 256>>>(dst, E);
    }
    scan1_kernel    <<<nb, SCAN_B>>>(n);
    scan2_kernel    <<<1, 128>>>(nb, n);
    scan3_kernel    <<<nb, SCAN_B>>>(n);
    fill_kernel     <<<(E + 255) / 256, 256>>>(src, dst, E);

    // layer 1
    wmma_gemm_kernel<128, false><<<(n + 127) / 128, 256, SM1>>>(x, W1, n);
    {
        int warps = (n + 1) / 2;
        agg1_kernel<<<(warps * 32 + 255) / 256, 256>>>(b1, n);
    }

    // layer 2
    wmma_gemm_kernel<64, true><<<(n + 127) / 128, 256, SM2>>>(nullptr, W2, n);
    {
        int warps = (n + 3) / 4;
        agg2_kernel<<<(warps * 32 + 255) / 256, 256>>>(b2, out, n);
    }
}

// round 12
// speedup vs baseline: 2.0177x; 1.0282x over previous
#include <cuda_runtime.h>
#include <cuda_bf16.h>
#include <cuda_fp16.h>
#include <mma.h>
#include <cstdint>

using namespace nvcuda;

#define NNODES 100000
#define EMAX   1600000
#define KDIM   128
#define SCAN_B 1024

// ---------------- scratch (no allocation allowed) ----------------
__device__ __align__(16) float g_dinv[NNODES];
__device__            int   g_deg[NNODES];
__device__            int   g_off[NNODES + 1];
__device__            int   g_cur[NNODES];
__device__            int   g_srcl[EMAX];
__device__            int   g_bsum[128];
__device__            int   g_bpre[128];
__device__ __align__(16) __half g_tmp1h[(size_t)NNODES * 128];  // GEMM out (dinv*h), fp16
__device__ __align__(16) __half g_hacth[(size_t)NNODES * 128];  // relu(layer1) fp16 = GEMM2's A

// ---------------- degree ----------------
__global__ void deg_init_kernel(int n) {
    int i = blockIdx.x * blockDim.x + threadIdx.x;
    if (i < n) g_deg[i] = 0;
}
// 4 edges per thread via int4
__global__ void deg_count_kernel(const int* __restrict__ dst, int E) {
    int i4 = blockIdx.x * blockDim.x + threadIdx.x;
    int i = i4 * 4;
    if (i + 4 <= E) {
        int4 d = *(const int4*)(dst + i);
        atomicAdd(&g_deg[d.x], 1);
        atomicAdd(&g_deg[d.y], 1);
        atomicAdd(&g_deg[d.z], 1);
        atomicAdd(&g_deg[d.w], 1);
    } else {
        for (; i < E; i++) atomicAdd(&g_deg[dst[i]], 1);
    }
}
__global__ void dinv_kernel(int n) {
    int i = blockIdx.x * blockDim.x + threadIdx.x;
    if (i < n) g_dinv[i] = rsqrtf((float)g_deg[i] + 1.0f);   // +1 self loop
}

// ---------------- multi-block exclusive scan ----------------
__global__ __launch_bounds__(SCAN_B) void scan1_kernel(int n) {
    __shared__ int sp[SCAN_B];
    int t = threadIdx.x;
    int i = blockIdx.x * SCAN_B + t;
    int d = (i < n) ? g_deg[i] : 0;
    sp[t] = d;
    __syncthreads();
#pragma unroll
    for (int off = 1; off < SCAN_B; off <<= 1) {
        int v = (t >= off) ? sp[t - off] : 0;
        __syncthreads();
        sp[t] += v;
        __syncthreads();
    }
    if (i < n) g_off[i] = sp[t] - d;
    if (t == SCAN_B - 1) g_bsum[blockIdx.x] = sp[t];
}
__global__ void scan2_kernel(int nb, int n) {
    __shared__ int sp[128];
    int t = threadIdx.x;
    int v = (t < nb) ? g_bsum[t] : 0;
    sp[t] = v;
    __syncthreads();
#pragma unroll
    for (int off = 1; off < 128; off <<= 1) {
        int u = (t >= off) ? sp[t - off] : 0;
        __syncthreads();
        sp[t] += u;
        __syncthreads();
    }
    if (t < nb) g_bpre[t] = sp[t] - v;
    if (t == nb - 1) g_off[n] = sp[t];
}
__global__ __launch_bounds__(SCAN_B) void scan3_kernel(int n) {
    int i = blockIdx.x * SCAN_B + threadIdx.x;
    if (i < n) {
        g_off[i] += g_bpre[blockIdx.x];
        g_cur[i] = 0;
    }
}

// ---------------- CSR fill ----------------
__global__ void fill_kernel(const int* __restrict__ src,
                            const int* __restrict__ dst, int E) {
    int i = blockIdx.x * blockDim.x + threadIdx.x;
    if (i < E) {
        int d = dst[i];
        int pos = atomicAdd(&g_cur[d], 1);
        g_srcl[g_off[d] + pos] = src[i];
    }
}

// ---------------- WMMA GEMM, dinv-scaled fp16 epilogue ----------------
// g_tmp1h[r, 0:BN] = fp16( dinv[r] * (A[r,:] @ W) ),  A: [M,128], W: [128,BN] fp32
template<int BN, bool AHALF>
__global__ __launch_bounds__(256) void wmma_gemm_kernel(
        const float* __restrict__ Aptr, const float* __restrict__ W, int M)
{
    constexpr int AS = 136;
    constexpr int BS = BN + 8;
    constexpr int CS = BN + 8;
    constexpr int NF = BN / 32;
    extern __shared__ __half smh[];
    __half* Asm = smh;
    __half* Wsm = smh + 128 * AS;
    float*  Csm = (float*)smh;

    int tid = threadIdx.x;
    int warp = tid >> 5;
    int wm = (warp >> 1) * 32;
    int wn = (warp & 1) * (BN / 2);
    int m0 = blockIdx.x * 128;

    if constexpr (AHALF) {
        const __half* Ah = g_hacth;
        for (int idx = tid; idx < 128 * 16; idx += 256) {
            int r = idx >> 4, c8 = (idx & 15) * 8;
            uint4 u = make_uint4(0u, 0u, 0u, 0u);
            if (m0 + r < M) u = *(const uint4*)(Ah + (size_t)(m0 + r) * 128 + c8);
            *(uint4*)(Asm + r * AS + c8) = u;
        }
    } else {
        for (int idx = tid; idx < 128 * 32; idx += 256) {
            int r = idx >> 5, c4 = (idx & 31) * 4;
            float4 v = make_float4(0.f, 0.f, 0.f, 0.f);
            if (m0 + r < M) v = *(const float4*)(Aptr + (size_t)(m0 + r) * 128 + c4);
            __half2 p0 = __floats2half2_rn(v.x, v.y);
            __half2 p1 = __floats2half2_rn(v.z, v.w);
            uint2 u; u.x = *(unsigned*)&p0; u.y = *(unsigned*)&p1;
            *(uint2*)(Asm + r * AS + c4) = u;
        }
    }
    for (int idx = tid; idx < 128 * (BN / 4); idx += 256) {
        int r = idx / (BN / 4), c4 = (idx % (BN / 4)) * 4;
        float4 v = *(const float4*)(W + (size_t)r * BN + c4);
        __half2 p0 = __floats2half2_rn(v.x, v.y);
        __half2 p1 = __floats2half2_rn(v.z, v.w);
        uint2 u; u.x = *(unsigned*)&p0; u.y = *(unsigned*)&p1;
        *(uint2*)(Wsm + r * BS + c4) = u;
    }
    __syncthreads();

    wmma::fragment<wmma::accumulator, 16, 16, 16, float> c[2][NF];
#pragma unroll
    for (int i = 0; i < 2; i++)
#pragma unroll
        for (int j = 0; j < NF; j++) wmma::fill_fragment(c[i][j], 0.0f);

#pragma unroll
    for (int k = 0; k < 128; k += 16) {
        wmma::fragment<wmma::matrix_a, 16, 16, 16, __half, wmma::row_major> a[2];
#pragma unroll
        for (int i = 0; i < 2; i++)
            wmma::load_matrix_sync(a[i], Asm + (wm + i * 16) * AS + k, AS);
#pragma unroll
        for (int j = 0; j < NF; j++) {
            wmma::fragment<wmma::matrix_b, 16, 16, 16, __half, wmma::row_major> b;
            wmma::load_matrix_sync(b, Wsm + k * BS + wn + j * 16, BS);
#pragma unroll
            for (int i = 0; i < 2; i++)
                wmma::mma_sync(c[i][j], a[i], b, c[i][j]);
        }
    }

    __syncthreads();
#pragma unroll
    for (int i = 0; i < 2; i++)
#pragma unroll
        for (int j = 0; j < NF; j++)
            wmma::store_matrix_sync(Csm + (wm + i * 16) * CS + wn + j * 16,
                                    c[i][j], CS, wmma::mem_row_major);
    __syncthreads();

    for (int idx = tid; idx < 128 * (BN / 2); idx += 256) {
        int r = idx / (BN / 2), c2 = (idx % (BN / 2)) * 2;
        int gr = m0 + r;
        if (gr < M) {
            float s = g_dinv[gr];
            float2 v = *(float2*)(Csm + r * CS + c2);
            __half2 h = __floats2half2_rn(v.x * s, v.y * s);
            *(unsigned*)(g_tmp1h + (size_t)gr * BN + c2) = *(unsigned*)&h;
        }
    }
}

// ---------------- gather aggregation (uint4 = 8 halves per lane) ----------
__device__ __forceinline__ void acc_u4(float* s, uint4 u) {
    __half2* h = (__half2*)&u;
#pragma unroll
    for (int i = 0; i < 4; i++) {
        float2 f = __half22float2(h[i]);
        s[2 * i]     += f.x;
        s[2 * i + 1] += f.y;
    }
}

// layer 1: 2 nodes per warp, 16 lanes/node, 8 cols/lane; writes fp16 hact
__global__ void agg1_kernel(const float* __restrict__ b1, int n) {
    int w = (int)((blockIdx.x * (unsigned)blockDim.x + threadIdx.x) >> 5);
    int lane = threadIdx.x & 31;
    int d = w * 2 + (lane >> 4);
    int hl = lane & 15;
    if (d >= n) return;
    const uint4* base = (const uint4*)g_tmp1h;
    float s[8] = {0, 0, 0, 0, 0, 0, 0, 0};
    acc_u4(s, base[(size_t)d * 16 + hl]);       // self loop
    int j = g_off[d], end = g_off[d + 1];
    for (; j + 4 <= end; j += 4) {
        int s0 = g_srcl[j], s1 = g_srcl[j + 1], s2 = g_srcl[j + 2], s3 = g_srcl[j + 3];
        uint4 u0 = base[(size_t)s0 * 16 + hl];
        uint4 u1 = base[(size_t)s1 * 16 + hl];
        uint4 u2 = base[(size_t)s2 * 16 + hl];
        uint4 u3 = base[(size_t)s3 * 16 + hl];
        acc_u4(s, u0); acc_u4(s, u1); acc_u4(s, u2); acc_u4(s, u3);
    }
    for (; j < end; j++) acc_u4(s, base[(size_t)g_srcl[j] * 16 + hl]);
    float sc = g_dinv[d];
    float4 ba = ((const float4*)b1)[hl * 2];
    float4 bbv = ((const float4*)b1)[hl * 2 + 1];
    float o[8];
    o[0] = fmaxf(fmaf(sc, s[0], ba.x), 0.f);
    o[1] = fmaxf(fmaf(sc, s[1], ba.y), 0.f);
    o[2] = fmaxf(fmaf(sc, s[2], ba.z), 0.f);
    o[3] = fmaxf(fmaf(sc, s[3], ba.w), 0.f);
    o[4] = fmaxf(fmaf(sc, s[4], bbv.x), 0.f);
    o[5] = fmaxf(fmaf(sc, s[5], bbv.y), 0.f);
    o[6] = fmaxf(fmaf(sc, s[6], bbv.z), 0.f);
    o[7] = fmaxf(fmaf(sc, s[7], bbv.w), 0.f);
    __half2 p0 = __floats2half2_rn(o[0], o[1]);
    __half2 p1 = __floats2half2_rn(o[2], o[3]);
    __half2 p2 = __floats2half2_rn(o[4], o[5]);
    __half2 p3 = __floats2half2_rn(o[6], o[7]);
    uint4 u;
    u.x = *(unsigned*)&p0; u.y = *(unsigned*)&p1;
    u.z = *(unsigned*)&p2; u.w = *(unsigned*)&p3;
    ((uint4*)g_hacth)[(size_t)d * 16 + hl] = u;
}

// layer 2: 4 nodes per warp, 8 lanes/node, 8 cols/lane; fp32 output
__global__ void agg2_kernel(const float* __restrict__ b2, float* __restrict__ out, int n) {
    int w = (int)((blockIdx.x * (unsigned)blockDim.x + threadIdx.x) >> 5);
    int lane = threadIdx.x & 31;
    int d = w * 4 + (lane >> 3);
    int hl = lane & 7;
    if (d >= n) return;
    const uint4* base = (const uint4*)g_tmp1h;
    float s[8] = {0, 0, 0, 0, 0, 0, 0, 0};
    acc_u4(s, base[(size_t)d * 8 + hl]);        // self loop
    int j = g_off[d], end = g_off[d + 1];
    for (; j + 4 <= end; j += 4) {
        int s0 = g_srcl[j], s1 = g_srcl[j + 1], s2 = g_srcl[j + 2], s3 = g_srcl[j + 3];
        uint4 u0 = base[(size_t)s0 * 8 + hl];
        uint4 u1 = base[(size_t)s1 * 8 + hl];
        uint4 u2 = base[(size_t)s2 * 8 + hl];
        uint4 u3 = base[(size_t)s3 * 8 + hl];
        acc_u4(s, u0); acc_u4(s, u1); acc_u4(s, u2); acc_u4(s, u3);
    }
    for (; j < end; j++) acc_u4(s, base[(size_t)g_srcl[j] * 8 + hl]);
    float sc = g_dinv[d];
    float4 ba = ((const float4*)b2)[hl * 2];
    float4 bbv = ((const float4*)b2)[hl * 2 + 1];
    float4 o0, o1;
    o0.x = fmaf(sc, s[0], ba.x);
    o0.y = fmaf(sc, s[1], ba.y);
    o0.z = fmaf(sc, s[2], ba.z);
    o0.w = fmaf(sc, s[3], ba.w);
    o1.x = fmaf(sc, s[4], bbv.x);
    o1.y = fmaf(sc, s[5], bbv.y);
    o1.z = fmaf(sc, s[6], bbv.z);
    o1.w = fmaf(sc, s[7], bbv.w);
    float4* op = (float4*)(out + (size_t)d * 64 + hl * 8);
    op[0] = o0;
    op[1] = o1;
}

// ---------------- launch ----------------
extern "C" void kernel_launch(void* const* d_in, const int* in_sizes, int n_in,
                              void* d_out, int out_size)
{
    const float* x  = (const float*)d_in[0];
    const int*   ei = (const int*)d_in[1];     // int32 (JAX coerces int64->int32)
    const float* W1 = (const float*)d_in[2];
    const float* b1 = (const float*)d_in[3];
    const float* W2 = (const float*)d_in[4];
    const float* b2 = (const float*)d_in[5];
    float* out = (float*)d_out;

    int n = in_sizes[0] / 128;   // 100000
    int E = in_sizes[1] / 2;     // 1600000
    const int* src = ei;
    const int* dst = ei + E;
    int nb = (n + SCAN_B - 1) / SCAN_B;

    constexpr int SM1 = 69632;
    constexpr int SM2 = 53248;
    cudaFuncSetAttribute(wmma_gemm_kernel<128, false>, cudaFuncAttributeMaxDynamicSharedMemorySize, SM1);
    cudaFuncSetAttribute(wmma_gemm_kernel<64, true>,   cudaFuncAttributeMaxDynamicSharedMemorySize, SM2);

    // side stream + fork/join events (host-side handles, created once; the
    // captured work is identical every call)
    static cudaStream_t s2 = nullptr;
    static cudaEvent_t evF = nullptr, evJ = nullptr;
    if (s2 == nullptr) {
        cudaStreamCreateWithFlags(&s2, cudaStreamNonBlocking);
        cudaEventCreateWithFlags(&evF, cudaEventDisableTiming);
        cudaEventCreateWithFlags(&evJ, cudaEventDisableTiming);
    }

    // ---- sequential prefix: degree + dinv (GEMM1's only dependency) ----
    deg_init_kernel <<<(n + 255) / 256, 256>>>(n);
    {
        int t4 = (E + 3) / 4;
        deg_count_kernel<<<(t4 + 255) / 256, 256>>>(dst, E);
    }
    dinv_kernel<<<(n + 255) / 256, 256>>>(n);

    // ---- fork: GEMM1 on side stream, CSR build on main stream ----
    cudaEventRecord(evF, 0);
    cudaStreamWaitEvent(s2, evF, 0);
    wmma_gemm_kernel<128, false><<<(n + 127) / 128, 256, SM1, s2>>>(x, W1, n);
    cudaEventRecord(evJ, s2);

    scan1_kernel<<<nb, SCAN_B>>>(n);
    scan2_kernel<<<1, 128>>>(nb, n);
    scan3_kernel<<<nb, SCAN_B>>>(n);
    fill_kernel <<<(E + 255) / 256, 256>>>(src, dst, E);

    // ---- join ----
    cudaStreamWaitEvent(0, evJ, 0);

    // layer 1 aggregation
    {
        int warps = (n + 1) / 2;
        agg1_kernel<<<(warps * 32 + 255) / 256, 256>>>(b1, n);
    }

    // layer 2
    wmma_gemm_kernel<64, true><<<(n + 127) / 128, 256, SM2>>>(nullptr, W2, n);
    {
        int warps = (n + 3) / 4;
        agg2_kernel<<<(warps * 32 + 255) / 256, 256>>>(b2, out, n);
    }
}

// round 13
// speedup vs baseline: 2.7978x; 1.3866x over previous
#include <cuda_runtime.h>
#include <cuda_bf16.h>
#include <cuda_fp16.h>
#include <mma.h>
#include <cstdint>

using namespace nvcuda;

#define NNODES 100000
#define EMAX   1600000
#define KDIM   128
#define SCAN_B 1024

// ---------------- scratch (no allocation allowed) ----------------
__device__ __align__(16) float g_dinv[NNODES];
__device__            int   g_deg[NNODES];
__device__            int   g_off[NNODES + 1];
__device__            int   g_cur[NNODES];
__device__            int   g_srcl[EMAX];
__device__            int   g_bsum[128];
__device__            int   g_bpre[128];
__device__ __align__(16) __half g_tmp1h[(size_t)NNODES * 128];  // GEMM out (dinv*h), fp16
__device__ __align__(16) __half g_hacth[(size_t)NNODES * 128];  // relu(layer1) fp16 = GEMM2's A

// ---------------- degree ----------------
__global__ void deg_init_kernel(int n) {
    int i = blockIdx.x * blockDim.x + threadIdx.x;
    if (i < n) g_deg[i] = 0;
}
__global__ void deg_count_kernel(const int* __restrict__ dst, int E) {
    int i4 = blockIdx.x * blockDim.x + threadIdx.x;
    int i = i4 * 4;
    if (i + 4 <= E) {
        int4 d = *(const int4*)(dst + i);
        atomicAdd(&g_deg[d.x], 1);
        atomicAdd(&g_deg[d.y], 1);
        atomicAdd(&g_deg[d.z], 1);
        atomicAdd(&g_deg[d.w], 1);
    } else {
        for (; i < E; i++) atomicAdd(&g_deg[dst[i]], 1);
    }
}
__global__ void dinv_kernel(int n) {
    int i = blockIdx.x * blockDim.x + threadIdx.x;
    if (i < n) g_dinv[i] = rsqrtf((float)g_deg[i] + 1.0f);   // +1 self loop
}

// ---------------- multi-block exclusive scan ----------------
__global__ __launch_bounds__(SCAN_B) void scan1_kernel(int n) {
    __shared__ int sp[SCAN_B];
    int t = threadIdx.x;
    int i = blockIdx.x * SCAN_B + t;
    int d = (i < n) ? g_deg[i] : 0;
    sp[t] = d;
    __syncthreads();
#pragma unroll
    for (int off = 1; off < SCAN_B; off <<= 1) {
        int v = (t >= off) ? sp[t - off] : 0;
        __syncthreads();
        sp[t] += v;
        __syncthreads();
    }
    if (i < n) g_off[i] = sp[t] - d;
    if (t == SCAN_B - 1) g_bsum[blockIdx.x] = sp[t];
}
__global__ void scan2_kernel(int nb, int n) {
    __shared__ int sp[128];
    int t = threadIdx.x;
    int v = (t < nb) ? g_bsum[t] : 0;
    sp[t] = v;
    __syncthreads();
#pragma unroll
    for (int off = 1; off < 128; off <<= 1) {
        int u = (t >= off) ? sp[t - off] : 0;
        __syncthreads();
        sp[t] += u;
        __syncthreads();
    }
    if (t < nb) g_bpre[t] = sp[t] - v;
    if (t == nb - 1) g_off[n] = sp[t];
}
__global__ __launch_bounds__(SCAN_B) void scan3_kernel(int n) {
    int i = blockIdx.x * SCAN_B + threadIdx.x;
    if (i < n) {
        g_off[i] += g_bpre[blockIdx.x];
        g_cur[i] = 0;
    }
}

// ---------------- CSR fill ----------------
__global__ void fill_kernel(const int* __restrict__ src,
                            const int* __restrict__ dst, int E) {
    int i = blockIdx.x * blockDim.x + threadIdx.x;
    if (i < E) {
        int d = dst[i];
        int pos = atomicAdd(&g_cur[d], 1);
        g_srcl[g_off[d] + pos] = src[i];
    }
}

// ---------------- WMMA GEMM (512 threads), dinv-scaled fp16 epilogue ------
// g_tmp1h[r, 0:BN] = fp16( dinv[r] * (A[r,:] @ W) ),  A: [M,128], W: [128,BN] fp32
template<int BN, bool AHALF>
__global__ __launch_bounds__(512) void wmma_gemm_kernel(
        const float* __restrict__ Aptr, const float* __restrict__ W, int M)
{
    constexpr int AS = 136;                 // A smem stride (halves)
    constexpr int BS = BN + 8;              // W smem stride (halves)
    constexpr int CS = BN + 8;              // C smem stride (floats)
    constexpr int NW = (BN == 128) ? 4 : 2; // warps along n
    constexpr int MW = 16 / NW;             // warps along m (4 or 8)
    constexpr int MI = 128 / (MW * 16);     // m-frags per warp (2 or 1)
    constexpr int NJ = BN / (NW * 16);      // n-frags per warp (2)
    extern __shared__ __half smh[];
    __half* Asm = smh;                      // 128 x AS halves
    __half* Wsm = smh + 128 * AS;           // 128 x BS halves
    float*  Csm = (float*)smh;              // 128 x CS floats (aliases after mma)

    int tid = threadIdx.x;                  // 512 threads
    int warp = tid >> 5;
    int wm = (warp / NW) * MI * 16;
    int wn = (warp % NW) * NJ * 16;
    int m0 = blockIdx.x * 128;

    // ---- stage A tile (fp16), zero-pad OOB rows ----
    if constexpr (AHALF) {
        const __half* Ah = g_hacth;
        for (int idx = tid; idx < 128 * 16; idx += 512) {   // uint4 = 8 halves
            int r = idx >> 4, c8 = (idx & 15) * 8;
            uint4 u = make_uint4(0u, 0u, 0u, 0u);
            if (m0 + r < M) u = *(const uint4*)(Ah + (size_t)(m0 + r) * 128 + c8);
            *(uint4*)(Asm + r * AS + c8) = u;
        }
    } else {
        for (int idx = tid; idx < 128 * 32; idx += 512) {   // float4 = 4 floats
            int r = idx >> 5, c4 = (idx & 31) * 4;
            float4 v = make_float4(0.f, 0.f, 0.f, 0.f);
            if (m0 + r < M) v = *(const float4*)(Aptr + (size_t)(m0 + r) * 128 + c4);
            __half2 p0 = __floats2half2_rn(v.x, v.y);
            __half2 p1 = __floats2half2_rn(v.z, v.w);
            uint2 u; u.x = *(unsigned*)&p0; u.y = *(unsigned*)&p1;
            *(uint2*)(Asm + r * AS + c4) = u;
        }
    }
    // ---- stage W (fp32 -> fp16) ----
    for (int idx = tid; idx < 128 * (BN / 4); idx += 512) {
        int r = idx / (BN / 4), c4 = (idx % (BN / 4)) * 4;
        float4 v = *(const float4*)(W + (size_t)r * BN + c4);
        __half2 p0 = __floats2half2_rn(v.x, v.y);
        __half2 p1 = __floats2half2_rn(v.z, v.w);
        uint2 u; u.x = *(unsigned*)&p0; u.y = *(unsigned*)&p1;
        *(uint2*)(Wsm + r * BS + c4) = u;
    }
    __syncthreads();

    wmma::fragment<wmma::accumulator, 16, 16, 16, float> c[MI][NJ];
#pragma unroll
    for (int i = 0; i < MI; i++)
#pragma unroll
        for (int j = 0; j < NJ; j++) wmma::fill_fragment(c[i][j], 0.0f);

#pragma unroll
    for (int k = 0; k < 128; k += 16) {
        wmma::fragment<wmma::matrix_a, 16, 16, 16, __half, wmma::row_major> a[MI];
#pragma unroll
        for (int i = 0; i < MI; i++)
            wmma::load_matrix_sync(a[i], Asm + (wm + i * 16) * AS + k, AS);
#pragma unroll
        for (int j = 0; j < NJ; j++) {
            wmma::fragment<wmma::matrix_b, 16, 16, 16, __half, wmma::row_major> b;
            wmma::load_matrix_sync(b, Wsm + k * BS + wn + j * 16, BS);
#pragma unroll
            for (int i = 0; i < MI; i++)
                wmma::mma_sync(c[i][j], a[i], b, c[i][j]);
        }
    }

    __syncthreads();    // staging dead; reuse as C stage
#pragma unroll
    for (int i = 0; i < MI; i++)
#pragma unroll
        for (int j = 0; j < NJ; j++)
            wmma::store_matrix_sync(Csm + (wm + i * 16) * CS + wn + j * 16,
                                    c[i][j], CS, wmma::mem_row_major);
    __syncthreads();

    // ---- epilogue: dinv scale, pack fp16, store ----
    for (int idx = tid; idx < 128 * (BN / 2); idx += 512) {
        int r = idx / (BN / 2), c2 = (idx % (BN / 2)) * 2;
        int gr = m0 + r;
        if (gr < M) {
            float s = g_dinv[gr];
            float2 v = *(float2*)(Csm + r * CS + c2);
            __half2 h = __floats2half2_rn(v.x * s, v.y * s);
            *(unsigned*)(g_tmp1h + (size_t)gr * BN + c2) = *(unsigned*)&h;
        }
    }
}

// ---------------- gather aggregation (uint4 = 8 halves per lane) ----------
__device__ __forceinline__ void acc_u4(float* s, uint4 u) {
    __half2* h = (__half2*)&u;
#pragma unroll
    for (int i = 0; i < 4; i++) {
        float2 f = __half22float2(h[i]);
        s[2 * i]     += f.x;
        s[2 * i + 1] += f.y;
    }
}

// layer 1: 2 nodes per warp, 16 lanes/node, 8 cols/lane; writes fp16 hact
__global__ void agg1_kernel(const float* __restrict__ b1, int n) {
    int w = (int)((blockIdx.x * (unsigned)blockDim.x + threadIdx.x) >> 5);
    int lane = threadIdx.x & 31;
    int d = w * 2 + (lane >> 4);
    int hl = lane & 15;
    if (d >= n) return;
    const uint4* base = (const uint4*)g_tmp1h;
    float s[8] = {0, 0, 0, 0, 0, 0, 0, 0};
    acc_u4(s, base[(size_t)d * 16 + hl]);       // self loop
    int j = g_off[d], end = g_off[d + 1];
    for (; j + 4 <= end; j += 4) {
        int s0 = g_srcl[j], s1 = g_srcl[j + 1], s2 = g_srcl[j + 2], s3 = g_srcl[j + 3];
        uint4 u0 = base[(size_t)s0 * 16 + hl];
        uint4 u1 = base[(size_t)s1 * 16 + hl];
        uint4 u2 = base[(size_t)s2 * 16 + hl];
        uint4 u3 = base[(size_t)s3 * 16 + hl];
        acc_u4(s, u0); acc_u4(s, u1); acc_u4(s, u2); acc_u4(s, u3);
    }
    for (; j < end; j++) acc_u4(s, base[(size_t)g_srcl[j] * 16 + hl]);
    float sc = g_dinv[d];
    float4 ba = ((const float4*)b1)[hl * 2];
    float4 bbv = ((const float4*)b1)[hl * 2 + 1];
    float o[8];
    o[0] = fmaxf(fmaf(sc, s[0], ba.x), 0.f);
    o[1] = fmaxf(fmaf(sc, s[1], ba.y), 0.f);
    o[2] = fmaxf(fmaf(sc, s[2], ba.z), 0.f);
    o[3] = fmaxf(fmaf(sc, s[3], ba.w), 0.f);
    o[4] = fmaxf(fmaf(sc, s[4], bbv.x), 0.f);
    o[5] = fmaxf(fmaf(sc, s[5], bbv.y), 0.f);
    o[6] = fmaxf(fmaf(sc, s[6], bbv.z), 0.f);
    o[7] = fmaxf(fmaf(sc, s[7], bbv.w), 0.f);
    __half2 p0 = __floats2half2_rn(o[0], o[1]);
    __half2 p1 = __floats2half2_rn(o[2], o[3]);
    __half2 p2 = __floats2half2_rn(o[4], o[5]);
    __half2 p3 = __floats2half2_rn(o[6], o[7]);
    uint4 u;
    u.x = *(unsigned*)&p0; u.y = *(unsigned*)&p1;
    u.z = *(unsigned*)&p2; u.w = *(unsigned*)&p3;
    ((uint4*)g_hacth)[(size_t)d * 16 + hl] = u;
}

// layer 2: 4 nodes per warp, 8 lanes/node, 8 cols/lane; fp32 output
__global__ void agg2_kernel(const float* __restrict__ b2, float* __restrict__ out, int n) {
    int w = (int)((blockIdx.x * (unsigned)blockDim.x + threadIdx.x) >> 5);
    int lane = threadIdx.x & 31;
    int d = w * 4 + (lane >> 3);
    int hl = lane & 7;
    if (d >= n) return;
    const uint4* base = (const uint4*)g_tmp1h;
    float s[8] = {0, 0, 0, 0, 0, 0, 0, 0};
    acc_u4(s, base[(size_t)d * 8 + hl]);        // self loop
    int j = g_off[d], end = g_off[d + 1];
    for (; j + 4 <= end; j += 4) {
        int s0 = g_srcl[j], s1 = g_srcl[j + 1], s2 = g_srcl[j + 2], s3 = g_srcl[j + 3];
        uint4 u0 = base[(size_t)s0 * 8 + hl];
        uint4 u1 = base[(size_t)s1 * 8 + hl];
        uint4 u2 = base[(size_t)s2 * 8 + hl];
        uint4 u3 = base[(size_t)s3 * 8 + hl];
        acc_u4(s, u0); acc_u4(s, u1); acc_u4(s, u2); acc_u4(s, u3);
    }
    for (; j < end; j++) acc_u4(s, base[(size_t)g_srcl[j] * 8 + hl]);
    float sc = g_dinv[d];
    float4 ba = ((const float4*)b2)[hl * 2];
    float4 bbv = ((const float4*)b2)[hl * 2 + 1];
    float4 o0, o1;
    o0.x = fmaf(sc, s[0], ba.x);
    o0.y = fmaf(sc, s[1], ba.y);
    o0.z = fmaf(sc, s[2], ba.z);
    o0.w = fmaf(sc, s[3], ba.w);
    o1.x = fmaf(sc, s[4], bbv.x);
    o1.y = fmaf(sc, s[5], bbv.y);
    o1.z = fmaf(sc, s[6], bbv.z);
    o1.w = fmaf(sc, s[7], bbv.w);
    float4* op = (float4*)(out + (size_t)d * 64 + hl * 8);
    op[0] = o0;
    op[1] = o1;
}

// ---------------- launch ----------------
extern "C" void kernel_launch(void* const* d_in, const int* in_sizes, int n_in,
                              void* d_out, int out_size)
{
    const float* x  = (const float*)d_in[0];
    const int*   ei = (const int*)d_in[1];     // int32 (JAX coerces int64->int32)
    const float* W1 = (const float*)d_in[2];
    const float* b1 = (const float*)d_in[3];
    const float* W2 = (const float*)d_in[4];
    const float* b2 = (const float*)d_in[5];
    float* out = (float*)d_out;

    int n = in_sizes[0] / 128;   // 100000
    int E = in_sizes[1] / 2;     // 1600000
    const int* src = ei;
    const int* dst = ei + E;
    int nb = (n + SCAN_B - 1) / SCAN_B;

    constexpr int SM1 = 69632;
    constexpr int SM2 = 53248;
    cudaFuncSetAttribute(wmma_gemm_kernel<128, false>, cudaFuncAttributeMaxDynamicSharedMemorySize, SM1);
    cudaFuncSetAttribute(wmma_gemm_kernel<64, true>,   cudaFuncAttributeMaxDynamicSharedMemorySize, SM2);

    // side stream + fork/join events (host-side handles, created once)
    static cudaStream_t s2 = nullptr;
    static cudaEvent_t evF = nullptr, evJ = nullptr;
    if (s2 == nullptr) {
        cudaStreamCreateWithFlags(&s2, cudaStreamNonBlocking);
        cudaEventCreateWithFlags(&evF, cudaEventDisableTiming);
        cudaEventCreateWithFlags(&evJ, cudaEventDisableTiming);
    }

    // ---- sequential prefix: degree + dinv (GEMM1's only dependency) ----
    deg_init_kernel <<<(n + 255) / 256, 256>>>(n);
    {
        int t4 = (E + 3) / 4;
        deg_count_kernel<<<(t4 + 255) / 256, 256>>>(dst, E);
    }
    dinv_kernel<<<(n + 255) / 256, 256>>>(n);

    // ---- fork: GEMM1 on side stream, CSR build on main stream ----
    cudaEventRecord(evF, 0);
    cudaStreamWaitEvent(s2, evF, 0);
    wmma_gemm_kernel<128, false><<<(n + 127) / 128, 512, SM1, s2>>>(x, W1, n);
    cudaEventRecord(evJ, s2);

    scan1_kernel<<<nb, SCAN_B>>>(n);
    scan2_kernel<<<1, 128>>>(nb, n);
    scan3_kernel<<<nb, SCAN_B>>>(n);
    fill_kernel <<<(E + 255) / 256, 256>>>(src, dst, E);

    // ---- join ----
    cudaStreamWaitEvent(0, evJ, 0);

    // layer 1 aggregation
    {
        int warps = (n + 1) / 2;
        agg1_kernel<<<(warps * 32 + 255) / 256, 256>>>(b1, n);
    }

    // layer 2
    wmma_gemm_kernel<64, true><<<(n + 127) / 128, 512, SM2>>>(nullptr, W2, n);
    {
        int warps = (n + 3) / 4;
        agg2_kernel<<<(warps * 32 + 255) / 256, 256>>>(b2, out, n);
    }
}

// round 15
// speedup vs baseline: 2.8053x; 1.0027x over previous
#include <cuda_runtime.h>
#include <cuda_bf16.h>
#include <cuda_fp16.h>
#include <mma.h>
#include <cstdint>

using namespace nvcuda;

#define NNODES 100000
#define EMAX   1600000
#define KDIM   128
#define SCAN_B 1024

// ---------------- scratch (no allocation allowed) ----------------
__device__ __align__(16) float g_dinv[NNODES];
__device__            int   g_deg[NNODES];
__device__            int   g_off[NNODES + 1];
__device__            int   g_cur[NNODES];
__device__            int   g_srcl[EMAX];
__device__            int   g_bsum[128];
__device__            int   g_bpre[128];
__device__ __align__(16) __half g_xh[(size_t)NNODES * 128];     // x in fp16 (GEMM1's A)
__device__ __align__(16) __half g_tmp1h[(size_t)NNODES * 128];  // GEMM out (dinv*h), fp16
__device__ __align__(16) __half g_hacth[(size_t)NNODES * 128];  // relu(layer1) fp16 = GEMM2's A

// ---------------- x -> fp16 conversion (pure streaming, no deps) ----------
__global__ void convert_x_kernel(const float* __restrict__ x, int total8) {
    int i = blockIdx.x * blockDim.x + threadIdx.x;   // one uint4 (8 halves) per thread
    if (i < total8) {
        float4 v0 = *(const float4*)(x + (size_t)i * 8);
        float4 v1 = *(const float4*)(x + (size_t)i * 8 + 4);
        __half2 p0 = __floats2half2_rn(v0.x, v0.y);
        __half2 p1 = __floats2half2_rn(v0.z, v0.w);
        __half2 p2 = __floats2half2_rn(v1.x, v1.y);
        __half2 p3 = __floats2half2_rn(v1.z, v1.w);
        uint4 u;
        u.x = *(unsigned*)&p0; u.y = *(unsigned*)&p1;
        u.z = *(unsigned*)&p2; u.w = *(unsigned*)&p3;
        ((uint4*)g_xh)[i] = u;
    }
}

// ---------------- degree ----------------
__global__ void deg_init_kernel(int n) {
    int i = blockIdx.x * blockDim.x + threadIdx.x;
    if (i < n) g_deg[i] = 0;
}
__global__ void deg_count_kernel(const int* __restrict__ dst, int E) {
    int i4 = blockIdx.x * blockDim.x + threadIdx.x;
    int i = i4 * 4;
    if (i + 4 <= E) {
        int4 d = *(const int4*)(dst + i);
        atomicAdd(&g_deg[d.x], 1);
        atomicAdd(&g_deg[d.y], 1);
        atomicAdd(&g_deg[d.z], 1);
        atomicAdd(&g_deg[d.w], 1);
    } else {
        for (; i < E; i++) atomicAdd(&g_deg[dst[i]], 1);
    }
}
__global__ void dinv_kernel(int n) {
    int i = blockIdx.x * blockDim.x + threadIdx.x;
    if (i < n) g_dinv[i] = rsqrtf((float)g_deg[i] + 1.0f);   // +1 self loop
}

// ---------------- multi-block exclusive scan ----------------
__global__ __launch_bounds__(SCAN_B) void scan1_kernel(int n) {
    __shared__ int sp[SCAN_B];
    int t = threadIdx.x;
    int i = blockIdx.x * SCAN_B + t;
    int d = (i < n) ? g_deg[i] : 0;
    sp[t] = d;
    __syncthreads();
#pragma unroll
    for (int off = 1; off < SCAN_B; off <<= 1) {
        int v = (t >= off) ? sp[t - off] : 0;
        __syncthreads();
        sp[t] += v;
        __syncthreads();
    }
    if (i < n) g_off[i] = sp[t] - d;
    if (t == SCAN_B - 1) g_bsum[blockIdx.x] = sp[t];
}
__global__ void scan2_kernel(int nb, int n) {
    __shared__ int sp[128];
    int t = threadIdx.x;
    int v = (t < nb) ? g_bsum[t] : 0;
    sp[t] = v;
    __syncthreads();
#pragma unroll
    for (int off = 1; off < 128; off <<= 1) {
        int u = (t >= off) ? sp[t - off] : 0;
        __syncthreads();
        sp[t] += u;
        __syncthreads();
    }
    if (t < nb) g_bpre[t] = sp[t] - v;
    if (t == nb - 1) g_off[n] = sp[t];
}
__global__ __launch_bounds__(SCAN_B) void scan3_kernel(int n) {
    int i = blockIdx.x * SCAN_B + threadIdx.x;
    if (i < n) {
        g_off[i] += g_bpre[blockIdx.x];
        g_cur[i] = 0;
    }
}

// ---------------- CSR fill ----------------
__global__ void fill_kernel(const int* __restrict__ src,
                            const int* __restrict__ dst, int E) {
    int i = blockIdx.x * blockDim.x + threadIdx.x;
    if (i < E) {
        int d = dst[i];
        int pos = atomicAdd(&g_cur[d], 1);
        g_srcl[g_off[d] + pos] = src[i];
    }
}

// ---------------- WMMA GEMM (512 threads), fp16 A, dinv-scaled fp16 out ---
// g_tmp1h[r, 0:BN] = fp16( dinv[r] * (A[r,:] @ W) )
// XSRC: A = g_xh (device symbol); else A = g_hacth. NEVER passed from host.
template<int BN, bool XSRC>
__global__ __launch_bounds__(512) void wmma_gemm_kernel(
        const float* __restrict__ W, int M)
{
    constexpr int AS = 136;                 // A smem stride (halves)
    constexpr int BS = BN + 8;              // W smem stride (halves)
    constexpr int CS = BN + 8;              // C smem stride (floats)
    constexpr int NW = (BN == 128) ? 4 : 2; // warps along n
    constexpr int MW = 16 / NW;             // warps along m
    constexpr int MI = 128 / (MW * 16);     // m-frags per warp
    constexpr int NJ = BN / (NW * 16);      // n-frags per warp
    extern __shared__ __half smh[];
    __half* Asm = smh;
    __half* Wsm = smh + 128 * AS;
    float*  Csm = (float*)smh;

    const __half* Ah = XSRC ? g_xh : g_hacth;   // device-side symbol resolution

    int tid = threadIdx.x;
    int warp = tid >> 5;
    int wm = (warp / NW) * MI * 16;
    int wn = (warp % NW) * NJ * 16;
    int m0 = blockIdx.x * 128;

    // ---- stage A tile (fp16, uint4 = 8 halves), zero-pad OOB rows ----
    for (int idx = tid; idx < 128 * 16; idx += 512) {
        int r = idx >> 4, c8 = (idx & 15) * 8;
        uint4 u = make_uint4(0u, 0u, 0u, 0u);
        if (m0 + r < M) u = *(const uint4*)(Ah + (size_t)(m0 + r) * 128 + c8);
        *(uint4*)(Asm + r * AS + c8) = u;
    }
    // ---- stage W (fp32 -> fp16) ----
    for (int idx = tid; idx < 128 * (BN / 4); idx += 512) {
        int r = idx / (BN / 4), c4 = (idx % (BN / 4)) * 4;
        float4 v = *(const float4*)(W + (size_t)r * BN + c4);
        __half2 p0 = __floats2half2_rn(v.x, v.y);
        __half2 p1 = __floats2half2_rn(v.z, v.w);
        uint2 u; u.x = *(unsigned*)&p0; u.y = *(unsigned*)&p1;
        *(uint2*)(Wsm + r * BS + c4) = u;
    }
    __syncthreads();

    wmma::fragment<wmma::accumulator, 16, 16, 16, float> c[MI][NJ];
#pragma unroll
    for (int i = 0; i < MI; i++)
#pragma unroll
        for (int j = 0; j < NJ; j++) wmma::fill_fragment(c[i][j], 0.0f);

#pragma unroll
    for (int k = 0; k < 128; k += 16) {
        wmma::fragment<wmma::matrix_a, 16, 16, 16, __half, wmma::row_major> a[MI];
#pragma unroll
        for (int i = 0; i < MI; i++)
            wmma::load_matrix_sync(a[i], Asm + (wm + i * 16) * AS + k, AS);
#pragma unroll
        for (int j = 0; j < NJ; j++) {
            wmma::fragment<wmma::matrix_b, 16, 16, 16, __half, wmma::row_major> b;
            wmma::load_matrix_sync(b, Wsm + k * BS + wn + j * 16, BS);
#pragma unroll
            for (int i = 0; i < MI; i++)
                wmma::mma_sync(c[i][j], a[i], b, c[i][j]);
        }
    }

    __syncthreads();    // staging dead; reuse as C stage
#pragma unroll
    for (int i = 0; i < MI; i++)
#pragma unroll
        for (int j = 0; j < NJ; j++)
            wmma::store_matrix_sync(Csm + (wm + i * 16) * CS + wn + j * 16,
                                    c[i][j], CS, wmma::mem_row_major);
    __syncthreads();

    // ---- epilogue: dinv scale, pack fp16, store ----
    for (int idx = tid; idx < 128 * (BN / 2); idx += 512) {
        int r = idx / (BN / 2), c2 = (idx % (BN / 2)) * 2;
        int gr = m0 + r;
        if (gr < M) {
            float s = g_dinv[gr];
            float2 v = *(float2*)(Csm + r * CS + c2);
            __half2 h = __floats2half2_rn(v.x * s, v.y * s);
            *(unsigned*)(g_tmp1h + (size_t)gr * BN + c2) = *(unsigned*)&h;
        }
    }
}

// ---------------- gather aggregation (uint4 = 8 halves per lane) ----------
__device__ __forceinline__ void acc_u4(float* s, uint4 u) {
    __half2* h = (__half2*)&u;
#pragma unroll
    for (int i = 0; i < 4; i++) {
        float2 f = __half22float2(h[i]);
        s[2 * i]     += f.x;
        s[2 * i + 1] += f.y;
    }
}

// layer 1: 2 nodes per warp, 16 lanes/node, 8 cols/lane; writes fp16 hact
__global__ void agg1_kernel(const float* __restrict__ b1, int n) {
    int w = (int)((blockIdx.x * (unsigned)blockDim.x + threadIdx.x) >> 5);
    int lane = threadIdx.x & 31;
    int d = w * 2 + (lane >> 4);
    int hl = lane & 15;
    if (d >= n) return;
    const uint4* base = (const uint4*)g_tmp1h;
    float s[8] = {0, 0, 0, 0, 0, 0, 0, 0};
    acc_u4(s, base[(size_t)d * 16 + hl]);       // self loop
    int j = g_off[d], end = g_off[d + 1];
    for (; j + 4 <= end; j += 4) {
        int s0 = g_srcl[j], s1 = g_srcl[j + 1], s2 = g_srcl[j + 2], s3 = g_srcl[j + 3];
        uint4 u0 = base[(size_t)s0 * 16 + hl];
        uint4 u1 = base[(size_t)s1 * 16 + hl];
        uint4 u2 = base[(size_t)s2 * 16 + hl];
        uint4 u3 = base[(size_t)s3 * 16 + hl];
        acc_u4(s, u0); acc_u4(s, u1); acc_u4(s, u2); acc_u4(s, u3);
    }
    for (; j < end; j++) acc_u4(s, base[(size_t)g_srcl[j] * 16 + hl]);
    float sc = g_dinv[d];
    float4 ba = ((const float4*)b1)[hl * 2];
    float4 bbv = ((const float4*)b1)[hl * 2 + 1];
    float o[8];
    o[0] = fmaxf(fmaf(sc, s[0], ba.x), 0.f);
    o[1] = fmaxf(fmaf(sc, s[1], ba.y), 0.f);
    o[2] = fmaxf(fmaf(sc, s[2], ba.z), 0.f);
    o[3] = fmaxf(fmaf(sc, s[3], ba.w), 0.f);
    o[4] = fmaxf(fmaf(sc, s[4], bbv.x), 0.f);
    o[5] = fmaxf(fmaf(sc, s[5], bbv.y), 0.f);
    o[6] = fmaxf(fmaf(sc, s[6], bbv.z), 0.f);
    o[7] = fmaxf(fmaf(sc, s[7], bbv.w), 0.f);
    __half2 p0 = __floats2half2_rn(o[0], o[1]);
    __half2 p1 = __floats2half2_rn(o[2], o[3]);
    __half2 p2 = __floats2half2_rn(o[4], o[5]);
    __half2 p3 = __floats2half2_rn(o[6], o[7]);
    uint4 u;
    u.x = *(unsigned*)&p0; u.y = *(unsigned*)&p1;
    u.z = *(unsigned*)&p2; u.w = *(unsigned*)&p3;
    ((uint4*)g_hacth)[(size_t)d * 16 + hl] = u;
}

// layer 2: 4 nodes per warp, 8 lanes/node, 8 cols/lane; fp32 output
__global__ void agg2_kernel(const float* __restrict__ b2, float* __restrict__ out, int n) {
    int w = (int)((blockIdx.x * (unsigned)blockDim.x + threadIdx.x) >> 5);
    int lane = threadIdx.x & 31;
    int d = w * 4 + (lane >> 3);
    int hl = lane & 7;
    if (d >= n) return;
    const uint4* base = (const uint4*)g_tmp1h;
    float s[8] = {0, 0, 0, 0, 0, 0, 0, 0};
    acc_u4(s, base[(size_t)d * 8 + hl]);        // self loop
    int j = g_off[d], end = g_off[d + 1];
    for (; j + 4 <= end; j += 4) {
        int s0 = g_srcl[j], s1 = g_srcl[j + 1], s2 = g_srcl[j + 2], s3 = g_srcl[j + 3];
        uint4 u0 = base[(size_t)s0 * 8 + hl];
        uint4 u1 = base[(size_t)s1 * 8 + hl];
        uint4 u2 = base[(size_t)s2 * 8 + hl];
        uint4 u3 = base[(size_t)s3 * 8 + hl];
        acc_u4(s, u0); acc_u4(s, u1); acc_u4(s, u2); acc_u4(s, u3);
    }
    for (; j < end; j++) acc_u4(s, base[(size_t)g_srcl[j] * 8 + hl]);
    float sc = g_dinv[d];
    float4 ba = ((const float4*)b2)[hl * 2];
    float4 bbv = ((const float4*)b2)[hl * 2 + 1];
    float4 o0, o1;
    o0.x = fmaf(sc, s[0], ba.x);
    o0.y = fmaf(sc, s[1], ba.y);
    o0.z = fmaf(sc, s[2], ba.z);
    o0.w = fmaf(sc, s[3], ba.w);
    o1.x = fmaf(sc, s[4], bbv.x);
    o1.y = fmaf(sc, s[5], bbv.y);
    o1.z = fmaf(sc, s[6], bbv.z);
    o1.w = fmaf(sc, s[7], bbv.w);
    float4* op = (float4*)(out + (size_t)d * 64 + hl * 8);
    op[0] = o0;
    op[1] = o1;
}

// ---------------- launch ----------------
extern "C" void kernel_launch(void* const* d_in, const int* in_sizes, int n_in,
                              void* d_out, int out_size)
{
    const float* x  = (const float*)d_in[0];
    const int*   ei = (const int*)d_in[1];     // int32 (JAX coerces int64->int32)
    const float* W1 = (const float*)d_in[2];
    const float* b1 = (const float*)d_in[3];
    const float* W2 = (const float*)d_in[4];
    const float* b2 = (const float*)d_in[5];
    float* out = (float*)d_out;

    int n = in_sizes[0] / 128;   // 100000
    int E = in_sizes[1] / 2;     // 1600000
    const int* src = ei;
    const int* dst = ei + E;
    int nb = (n + SCAN_B - 1) / SCAN_B;

    constexpr int SM1 = 69632;
    constexpr int SM2 = 53248;
    cudaFuncSetAttribute(wmma_gemm_kernel<128, true>, cudaFuncAttributeMaxDynamicSharedMemorySize, SM1);
    cudaFuncSetAttribute(wmma_gemm_kernel<64, false>, cudaFuncAttributeMaxDynamicSharedMemorySize, SM2);

    // side stream + fork/join events (host-side handles, created once)
    static cudaStream_t s2 = nullptr;
    static cudaEvent_t evF = nullptr, evD = nullptr, evJ = nullptr;
    if (s2 == nullptr) {
        cudaStreamCreateWithFlags(&s2, cudaStreamNonBlocking);
        cudaEventCreateWithFlags(&evF, cudaEventDisableTiming);
        cudaEventCreateWithFlags(&evD, cudaEventDisableTiming);
        cudaEventCreateWithFlags(&evJ, cudaEventDisableTiming);
    }

    // ---- fork at entry: x->fp16 conversion on s2 (no dependencies) ----
    cudaEventRecord(evF, 0);
    cudaStreamWaitEvent(s2, evF, 0);
    {
        int total8 = n * 16;   // n*128 halves / 8 per thread
        convert_x_kernel<<<(total8 + 255) / 256, 256, 0, s2>>>(x, total8);
    }

    // ---- main: degree + dinv ----
    deg_init_kernel <<<(n + 255) / 256, 256>>>(n);
    {
        int t4 = (E + 3) / 4;
        deg_count_kernel<<<(t4 + 255) / 256, 256>>>(dst, E);
    }
    dinv_kernel<<<(n + 255) / 256, 256>>>(n);
    cudaEventRecord(evD, 0);

    // ---- s2: GEMM1 (after conversion on s2 + dinv from main) ----
    cudaStreamWaitEvent(s2, evD, 0);
    wmma_gemm_kernel<128, true><<<(n + 127) / 128, 512, SM1, s2>>>(W1, n);
    cudaEventRecord(evJ, s2);

    // ---- main: CSR build (overlaps GEMM1) ----
    scan1_kernel<<<nb, SCAN_B>>>(n);
    scan2_kernel<<<1, 128>>>(nb, n);
    scan3_kernel<<<nb, SCAN_B>>>(n);
    fill_kernel <<<(E + 255) / 256, 256>>>(src, dst, E);

    // ---- join ----
    cudaStreamWaitEvent(0, evJ, 0);

    // layer 1 aggregation
    {
        int warps = (n + 1) / 2;
        agg1_kernel<<<(warps * 32 + 255) / 256, 256>>>(b1, n);
    }

    // layer 2
    wmma_gemm_kernel<64, false><<<(n + 127) / 128, 512, SM2>>>(W2, n);
    {
        int warps = (n + 3) / 4;
        agg2_kernel<<<(warps * 32 + 255) / 256, 256>>>(b2, out, n);
    }
}